// round 11
// baseline (speedup 1.0000x reference)
#include <cuda_runtime.h>

// 8192x8192 fp32 input; 10 3x3 SAME convs; 4 2x2 maxpools.
// Stages: [conv,conv,pool] x2 then [conv,conv,conv,pool] x2.
// R11 = R8 (best: 194.9us) + MINCTA=5 for K=2 stages (forces 40 regs ->
//       5 CTAs/SM = 50 warps, +25% latency hiding on stages A/B).

__device__ float g_buf0[4096u * 4096u];
__device__ float g_buf1[2048u * 2048u];
__device__ float g_buf2[1024u * 1024u];

#define NT 320                 // threads per block (10 warps)
#define BD 72                  // smem buffer dim (stride), 16B-aligned rows
#define STRIPS 17              // 17 x 17 threads x (4x4 px) cover 68x68
#define NACT (STRIPS * STRIPS) // 289 active conv threads

// Load 8 consecutive floats (two aligned float4) from smem.
__device__ __forceinline__ void ld8(float* d, const float* p) {
    float4 a = *(const float4*)(p);
    float4 b = *(const float4*)(p + 4);
    d[0] = a.x; d[1] = a.y; d[2] = a.z; d[3] = a.w;
    d[4] = b.x; d[5] = b.y; d[6] = b.z; d[7] = b.w;
}

__device__ __forceinline__ void conv_row(float v[4], const float* r0,
                                         const float* r1, const float* r2,
                                         const float k[9]) {
#pragma unroll
    for (int q = 0; q < 4; ++q) {
        v[q] = r0[q] * k[0] + r0[q + 1] * k[1] + r0[q + 2] * k[2]
             + r1[q] * k[3] + r1[q + 1] * k[4] + r1[q + 2] * k[5]
             + r2[q] * k[6] + r2[q + 1] * k[7] + r2[q + 2] * k[8];
    }
}

// One conv layer, shifted-origin: dst[r][x] = conv(src)[r+1][x+1].
// Reads ld8 at col 4s (window offset 0), stores aligned float4 at col 4s.
template <bool EDGE>
__device__ __forceinline__ void layer_mid(const float* __restrict__ src,
                                          float* __restrict__ dst,
                                          const float k[9], int s, int g,
                                          int ey0, int ex0, unsigned uw) {
    const float* sp = src + (4 * g) * BD + 4 * s;
    float r[3][8];
    ld8(r[0], sp);
    ld8(r[1], sp + BD);
#pragma unroll
    for (int j = 0; j < 4; ++j) {
        ld8(r[(j + 2) % 3], sp + (2 + j) * BD);
        float v[4];
        conv_row(v, r[j % 3], r[(j + 1) % 3], r[(j + 2) % 3], k);
        if (EDGE) {  // SAME zero-pad at the image boundary, per layer
            const bool rok = (unsigned)(ey0 + 4 * g + j) < uw;
#pragma unroll
            for (int q = 0; q < 4; ++q)
                if (!(rok && ((unsigned)(ex0 + 4 * s + q) < uw))) v[q] = 0.0f;
        }
        *(float4*)(dst + (4 * g + j) * BD + 4 * s) =
            make_float4(v[0], v[1], v[2], v[3]);
    }
}

// Last conv layer fused with 2x2 maxpool (interior blocks; s,g < 16).
__device__ __forceinline__ void layer_last_pool(const float* __restrict__ src,
                                                float* __restrict__ out,
                                                int outW, const float k[9],
                                                int s, int g, int oy, int ox) {
    const float* sp = src + (4 * g) * BD + 4 * s;
    float r[3][8];
    ld8(r[0], sp);
    ld8(r[1], sp + BD);
    float p[2][2];
#pragma unroll
    for (int j = 0; j < 4; ++j) {
        ld8(r[(j + 2) % 3], sp + (2 + j) * BD);
        float v[4];
        conv_row(v, r[j % 3], r[(j + 1) % 3], r[(j + 2) % 3], k);
        const int pr = j >> 1;
        float m0 = fmaxf(v[0], v[1]);
        float m1 = fmaxf(v[2], v[3]);
        if ((j & 1) == 0) { p[pr][0] = m0; p[pr][1] = m1; }
        else             { p[pr][0] = fmaxf(p[pr][0], m0);
                           p[pr][1] = fmaxf(p[pr][1], m1); }
    }
    float* op = out + (long)(oy + 2 * g) * outW + (ox + 2 * s);
    *(float2*)op = make_float2(p[0][0], p[0][1]);
    *(float2*)(op + outW) = make_float2(p[1][0], p[1][1]);
}

// Fused stage: K 3x3 convs (SAME at image boundary) + 2x2 maxpool.
// Block -> 32x32 pooled tile (64x64 pre-pool). EXT = 64 + 2K loaded extent.
template <int K, int MINCTA>
__global__ __launch_bounds__(NT, MINCTA)
void stage_kernel(const float* __restrict__ in, int inW,
                  float* __restrict__ out, int outW,
                  const float* __restrict__ w0,
                  const float* __restrict__ w1,
                  const float* __restrict__ w2) {
    constexpr int EXT = 64 + 2 * K;
    __shared__ float bufA[BD * BD];
    __shared__ float bufB[BD * BD];
    __shared__ float wts[27];

    const int tid = threadIdx.x;
    if (tid < K * 9) {
        const float* wp = (tid < 9) ? w0 : ((tid < 18) ? w1 : w2);
        wts[tid] = wp[tid % 9];
    }

    const int gx0 = blockIdx.x * 64 - K;
    const int gy0 = blockIdx.y * 64 - K;
    const unsigned uw = (unsigned)inW;  // square image
    const bool edge = (gx0 < 0) || (gy0 < 0) ||
                      (gx0 + EXT > inW) || (gy0 + EXT > inW);

    if (!edge) {
        // Interior: no zero-init needed. Validity trace: unwritten buffer
        // cells only ever feed intermediate rows/cols >= 66, which no later
        // layer tap that reaches the pooled output reads; loaded-but-unused
        // ld8 lanes are discarded in registers. Junk is finite.
        if (K == 2) {
            // gx0 even, and interior => gx0+71 <= inW-59: load the full
            // 72x72 window unconditionally with aligned float2.
            if (tid < 288) {
                const int tc = tid % 36;            // float2 column
                const int tr = tid / 36;            // 8 concurrent rows
                const float* gp = in + (long)(gy0 + tr) * inW + gx0 + 2 * tc;
                float* bp = bufA + tr * BD + 2 * tc;
#pragma unroll
                for (int r = 0; r < 9; ++r, gp += 8L * inW, bp += 8 * BD)
                    *(float2*)bp = *(const float2*)gp;
            }
        } else {
            // K=3: gx0 odd; masked to EXT (OOB otherwise), no image masks.
            for (int i = tid; i < BD * BD; i += NT) {
                int r = i / BD, c = i - r * BD;
                if (r < EXT && c < EXT)
                    bufA[i] = in[(long)(gy0 + r) * inW + (gx0 + c)];
            }
        }
    } else {
        // Edge: zero both buffers, masked scalar load (proven path).
        for (int i = tid; i < BD * BD; i += NT) {
            int r = i / BD, c = i - r * BD;
            float v = 0.0f;
            if (r < EXT && c < EXT) {
                int gy = gy0 + r, gx = gx0 + c;
                if ((unsigned)gy < uw && (unsigned)gx < uw)
                    v = in[(long)gy * inW + gx];
            }
            bufA[i] = v;
            bufB[i] = 0.0f;
        }
    }
    __syncthreads();

    const bool active = tid < NACT;
    const int s = tid % STRIPS;
    const int g = tid / STRIPS;
    const int ox = blockIdx.x * 32, oy = blockIdx.y * 32;

    float k[9];
    float* src = bufA;
    float* dst = bufB;

    // ---- layers 0 .. K-2 (to smem) ----
#pragma unroll
    for (int c = 0; c < K - 1; ++c) {
        if (active) {
#pragma unroll
            for (int m = 0; m < 9; ++m) k[m] = wts[c * 9 + m];
            if (edge) layer_mid<true >(src, dst, k, s, g,
                                       gy0 + c + 1, gx0 + c + 1, uw);
            else      layer_mid<false>(src, dst, k, s, g, 0, 0, uw);
        }
        __syncthreads();
        float* t = src; src = dst; dst = t;
    }

    // ---- last layer ----
    if (!edge) {
        if (s < 16 && g < 16 && active) {
#pragma unroll
            for (int m = 0; m < 9; ++m) k[m] = wts[(K - 1) * 9 + m];
            layer_last_pool(src, out, outW, k, s, g, oy, ox);
        }
        // no further smem use; no sync needed before exit
    } else {
        if (active) {
#pragma unroll
            for (int m = 0; m < 9; ++m) k[m] = wts[(K - 1) * 9 + m];
            layer_mid<true>(src, dst, k, s, g, gy0 + K, gx0 + K, uw);
        }
        __syncthreads();
        // Pool over dst [0,64)^2 (buf coord 0 == abs blockIdx*64).
        for (int i = tid; i < 1024; i += NT) {
            int py = i >> 5, px = i & 31;
            const float* p = dst + (2 * py) * BD + 2 * px;
            float m = fmaxf(fmaxf(p[0], p[1]), fmaxf(p[BD], p[BD + 1]));
            out[(long)(oy + py) * outW + ox + px] = m;
        }
    }
}

extern "C" void kernel_launch(void* const* d_in, const int* in_sizes, int n_in,
                              void* d_out, int out_size) {
    const float* x = (const float*)d_in[0];
    const float* w[10];
    for (int i = 0; i < 10; ++i) w[i] = (const float*)d_in[1 + i];

    float *b0, *b1, *b2;
    cudaGetSymbolAddress((void**)&b0, g_buf0);
    cudaGetSymbolAddress((void**)&b1, g_buf1);
    cudaGetSymbolAddress((void**)&b2, g_buf2);

    float* outp = (float*)d_out;

    // K=2 stages: MINCTA=5 (40-reg target, 5 CTAs/SM).
    stage_kernel<2, 5><<<dim3(128, 128), NT>>>(x,  8192, b0,  4096, w[0], w[1], nullptr);
    stage_kernel<2, 5><<<dim3(64, 64),   NT>>>(b0, 4096, b1,  2048, w[2], w[3], nullptr);
    // K=3 stages: proven MINCTA=4 (48 regs, no spill risk).
    stage_kernel<3, 4><<<dim3(32, 32),   NT>>>(b1, 2048, b2,  1024, w[4], w[5], w[6]);
    stage_kernel<3, 4><<<dim3(16, 16),   NT>>>(b2, 1024, outp, 512, w[7], w[8], w[9]);
}

// round 12
// speedup vs baseline: 1.0653x; 1.0653x over previous
#include <cuda_runtime.h>

// 8192x8192 fp32 input; 10 3x3 SAME convs; 4 2x2 maxpools.
// Stages: [conv,conv,pool] x2 then [conv,conv,conv,pool] x2.
// R12 = R8 (best, 194.9us) with the stage kernel parameterized by tile size;
//       stages C,D run TO=16 / 128-thread CTAs (grid x4) to fix the
//       latency-inflated small-grid tail. Stages A,B byte-identical to R8.

__device__ float g_buf0[4096u * 4096u];
__device__ float g_buf1[2048u * 2048u];
__device__ float g_buf2[1024u * 1024u];

// Load 8 consecutive floats (two aligned float4) from smem.
__device__ __forceinline__ void ld8(float* d, const float* p) {
    float4 a = *(const float4*)(p);
    float4 b = *(const float4*)(p + 4);
    d[0] = a.x; d[1] = a.y; d[2] = a.z; d[3] = a.w;
    d[4] = b.x; d[5] = b.y; d[6] = b.z; d[7] = b.w;
}

__device__ __forceinline__ void conv_row(float v[4], const float* r0,
                                         const float* r1, const float* r2,
                                         const float k[9]) {
#pragma unroll
    for (int q = 0; q < 4; ++q) {
        v[q] = r0[q] * k[0] + r0[q + 1] * k[1] + r0[q + 2] * k[2]
             + r1[q] * k[3] + r1[q + 1] * k[4] + r1[q + 2] * k[5]
             + r2[q] * k[6] + r2[q + 1] * k[7] + r2[q + 2] * k[8];
    }
}

// One conv layer, shifted-origin: dst[r][x] = conv(src)[r+1][x+1].
template <int BD, bool EDGE>
__device__ __forceinline__ void layer_mid(const float* __restrict__ src,
                                          float* __restrict__ dst,
                                          const float k[9], int s, int g,
                                          int ey0, int ex0, unsigned uw) {
    const float* sp = src + (4 * g) * BD + 4 * s;
    float r[3][8];
    ld8(r[0], sp);
    ld8(r[1], sp + BD);
#pragma unroll
    for (int j = 0; j < 4; ++j) {
        ld8(r[(j + 2) % 3], sp + (2 + j) * BD);
        float v[4];
        conv_row(v, r[j % 3], r[(j + 1) % 3], r[(j + 2) % 3], k);
        if (EDGE) {  // SAME zero-pad at the image boundary, per layer
            const bool rok = (unsigned)(ey0 + 4 * g + j) < uw;
#pragma unroll
            for (int q = 0; q < 4; ++q)
                if (!(rok && ((unsigned)(ex0 + 4 * s + q) < uw))) v[q] = 0.0f;
        }
        *(float4*)(dst + (4 * g + j) * BD + 4 * s) =
            make_float4(v[0], v[1], v[2], v[3]);
    }
}

// Last conv layer fused with 2x2 maxpool (interior blocks; s,g < TO/2).
template <int BD>
__device__ __forceinline__ void layer_last_pool(const float* __restrict__ src,
                                                float* __restrict__ out,
                                                int outW, const float k[9],
                                                int s, int g, int oy, int ox) {
    const float* sp = src + (4 * g) * BD + 4 * s;
    float r[3][8];
    ld8(r[0], sp);
    ld8(r[1], sp + BD);
    float p[2][2];
#pragma unroll
    for (int j = 0; j < 4; ++j) {
        ld8(r[(j + 2) % 3], sp + (2 + j) * BD);
        float v[4];
        conv_row(v, r[j % 3], r[(j + 1) % 3], r[(j + 2) % 3], k);
        const int pr = j >> 1;
        float m0 = fmaxf(v[0], v[1]);
        float m1 = fmaxf(v[2], v[3]);
        if ((j & 1) == 0) { p[pr][0] = m0; p[pr][1] = m1; }
        else             { p[pr][0] = fmaxf(p[pr][0], m0);
                           p[pr][1] = fmaxf(p[pr][1], m1); }
    }
    float* op = out + (long)(oy + 2 * g) * outW + (ox + 2 * s);
    *(float2*)op = make_float2(p[0][0], p[0][1]);
    *(float2*)(op + outW) = make_float2(p[1][0], p[1][1]);
}

// Fused stage: K 3x3 convs (SAME at image boundary) + 2x2 maxpool.
// Block -> TO x TO pooled tile (2TO x 2TO pre-pool).
// STRIPS*4 covers the widest needed valid region (2TO + 2(K-1));
// BD >= max(EXT, 4*STRIPS+4) so every ld8/store stays in bounds.
template <int K, int TO, int NT, int MINCTA>
__global__ __launch_bounds__(NT, MINCTA)
void stage_kernel(const float* __restrict__ in, int inW,
                  float* __restrict__ out, int outW,
                  const float* __restrict__ w0,
                  const float* __restrict__ w1,
                  const float* __restrict__ w2) {
    constexpr int EXT    = 2 * TO + 2 * K;
    constexpr int STRIPS = (2 * TO + 2 * (K - 1) + 3) / 4;
    constexpr int NACT   = STRIPS * STRIPS;
    constexpr int BDv    = (EXT > 4 * STRIPS + 4) ? EXT : (4 * STRIPS + 4);
    constexpr int BD     = (BDv + 3) & ~3;  // 16B-aligned rows

    __shared__ float bufA[BD * BD];
    __shared__ float bufB[BD * BD];
    __shared__ float wts[27];

    const int tid = threadIdx.x;
    if (tid < K * 9) {
        const float* wp = (tid < 9) ? w0 : ((tid < 18) ? w1 : w2);
        wts[tid] = wp[tid % 9];
    }

    const int gx0 = blockIdx.x * 2 * TO - K;
    const int gy0 = blockIdx.y * 2 * TO - K;
    const unsigned uw = (unsigned)inW;  // square image
    const bool edge = (gx0 < 0) || (gy0 < 0) ||
                      (gx0 + EXT > inW) || (gy0 + EXT > inW);

    if (!edge) {
        // Interior: no zero-init needed (junk halo cells never reach the
        // pooled output; values stay finite).
        if (K == 2 && TO == 32) {
            // gx0 even, interior => full 72x72 window in-image: unconditional
            // aligned float2 loads (proven R8 fast path).
            if (tid < 288) {
                const int tc = tid % 36;            // float2 column
                const int tr = tid / 36;            // 8 concurrent rows
                const float* gp = in + (long)(gy0 + tr) * inW + gx0 + 2 * tc;
                float* bp = bufA + tr * BD + 2 * tc;
#pragma unroll
                for (int r = 0; r < 9; ++r, gp += 8L * inW, bp += 8 * BD)
                    *(float2*)bp = *(const float2*)gp;
            }
        } else {
            // Masked to EXT only (no image masks needed in the interior).
            for (int i = tid; i < BD * BD; i += NT) {
                int r = i / BD, c = i - r * BD;
                if (r < EXT && c < EXT)
                    bufA[i] = in[(long)(gy0 + r) * inW + (gx0 + c)];
            }
        }
    } else {
        // Edge: zero both buffers, masked scalar load (proven path).
        for (int i = tid; i < BD * BD; i += NT) {
            int r = i / BD, c = i - r * BD;
            float v = 0.0f;
            if (r < EXT && c < EXT) {
                int gy = gy0 + r, gx = gx0 + c;
                if ((unsigned)gy < uw && (unsigned)gx < uw)
                    v = in[(long)gy * inW + gx];
            }
            bufA[i] = v;
            bufB[i] = 0.0f;
        }
    }
    __syncthreads();

    const bool active = tid < NACT;
    const int s = tid % STRIPS;
    const int g = tid / STRIPS;
    const int ox = blockIdx.x * TO, oy = blockIdx.y * TO;

    float k[9];
    float* src = bufA;
    float* dst = bufB;

    // ---- layers 0 .. K-2 (to smem) ----
#pragma unroll
    for (int c = 0; c < K - 1; ++c) {
        if (active) {
#pragma unroll
            for (int m = 0; m < 9; ++m) k[m] = wts[c * 9 + m];
            if (edge) layer_mid<BD, true >(src, dst, k, s, g,
                                           gy0 + c + 1, gx0 + c + 1, uw);
            else      layer_mid<BD, false>(src, dst, k, s, g, 0, 0, uw);
        }
        __syncthreads();
        float* t = src; src = dst; dst = t;
    }

    // ---- last layer ----
    if (!edge) {
        if (active && s < TO / 2 && g < TO / 2) {
#pragma unroll
            for (int m = 0; m < 9; ++m) k[m] = wts[(K - 1) * 9 + m];
            layer_last_pool<BD>(src, out, outW, k, s, g, oy, ox);
        }
        // no further smem use; no sync needed before exit
    } else {
        if (active) {
#pragma unroll
            for (int m = 0; m < 9; ++m) k[m] = wts[(K - 1) * 9 + m];
            layer_mid<BD, true>(src, dst, k, s, g, gy0 + K, gx0 + K, uw);
        }
        __syncthreads();
        // Pool over dst [0,2TO)^2 (buf coord 0 == abs blockIdx*2TO).
        for (int i = tid; i < TO * TO; i += NT) {
            int py = i / TO, px = i % TO;
            const float* p = dst + (2 * py) * BD + 2 * px;
            float m = fmaxf(fmaxf(p[0], p[1]), fmaxf(p[BD], p[BD + 1]));
            out[(long)(oy + py) * outW + ox + px] = m;
        }
    }
}

extern "C" void kernel_launch(void* const* d_in, const int* in_sizes, int n_in,
                              void* d_out, int out_size) {
    const float* x = (const float*)d_in[0];
    const float* w[10];
    for (int i = 0; i < 10; ++i) w[i] = (const float*)d_in[1 + i];

    float *b0, *b1, *b2;
    cudaGetSymbolAddress((void**)&b0, g_buf0);
    cudaGetSymbolAddress((void**)&b1, g_buf1);
    cudaGetSymbolAddress((void**)&b2, g_buf2);

    float* outp = (float*)d_out;

    // Stages A, B: proven R8 config (TO=32, 320 threads, 4 CTAs/SM).
    stage_kernel<2, 32, 320, 4><<<dim3(128, 128), 320>>>(x,  8192, b0, 4096, w[0], w[1], nullptr);
    stage_kernel<2, 32, 320, 4><<<dim3(64, 64),   320>>>(b0, 4096, b1, 2048, w[2], w[3], nullptr);
    // Stages C, D: TO=16, 128-thread CTAs -> 4096 / 1024 CTAs, ~40 warps/SM.
    stage_kernel<3, 16, 128, 8><<<dim3(64, 64),   128>>>(b1, 2048, b2, 1024, w[4], w[5], w[6]);
    stage_kernel<3, 16, 128, 8><<<dim3(32, 32),   128>>>(b2, 1024, outp, 512, w[7], w[8], w[9]);
}

// round 13
// speedup vs baseline: 1.0847x; 1.0183x over previous
#include <cuda_runtime.h>

// 8192x8192 fp32 input; 10 3x3 SAME convs; 4 2x2 maxpools.
// Stages: [conv,conv,pool] x2 then [conv,conv,conv,pool] x2.
// R13: stages A,B interior blocks fuse BOTH conv layers in registers
//      (1 barrier, no intermediate smem round-trip). Edge path = R8.
//      Stage C = R8 config, stage D = R12 config (measured better).

__device__ float g_buf0[4096u * 4096u];
__device__ float g_buf1[2048u * 2048u];
__device__ float g_buf2[1024u * 1024u];

#define NT 320
#define BD 72

// Load 8 consecutive floats (two aligned float4) from smem.
__device__ __forceinline__ void ld8(float* d, const float* p) {
    float4 a = *(const float4*)(p);
    float4 b = *(const float4*)(p + 4);
    d[0] = a.x; d[1] = a.y; d[2] = a.z; d[3] = a.w;
    d[4] = b.x; d[5] = b.y; d[6] = b.z; d[7] = b.w;
}

__device__ __forceinline__ void conv_row(float v[4], const float* r0,
                                         const float* r1, const float* r2,
                                         const float k[9]) {
#pragma unroll
    for (int q = 0; q < 4; ++q) {
        v[q] = r0[q] * k[0] + r0[q + 1] * k[1] + r0[q + 2] * k[2]
             + r1[q] * k[3] + r1[q + 1] * k[4] + r1[q + 2] * k[5]
             + r2[q] * k[6] + r2[q + 1] * k[7] + r2[q + 2] * k[8];
    }
}

// 6-wide conv row (for the register-resident layer-1).
__device__ __forceinline__ void l1row6(float o[6], const float* r0,
                                       const float* r1, const float* r2,
                                       const float k[9]) {
#pragma unroll
    for (int q = 0; q < 6; ++q) {
        o[q] = r0[q] * k[0] + r0[q + 1] * k[1] + r0[q + 2] * k[2]
             + r1[q] * k[3] + r1[q + 1] * k[4] + r1[q + 2] * k[5]
             + r2[q] * k[6] + r2[q + 1] * k[7] + r2[q + 2] * k[8];
    }
}

// ---- proven R8 edge-path helpers ----
template <int BDT, bool EDGE>
__device__ __forceinline__ void layer_mid(const float* __restrict__ src,
                                          float* __restrict__ dst,
                                          const float k[9], int s, int g,
                                          int ey0, int ex0, unsigned uw) {
    const float* sp = src + (4 * g) * BDT + 4 * s;
    float r[3][8];
    ld8(r[0], sp);
    ld8(r[1], sp + BDT);
#pragma unroll
    for (int j = 0; j < 4; ++j) {
        ld8(r[(j + 2) % 3], sp + (2 + j) * BDT);
        float v[4];
        conv_row(v, r[j % 3], r[(j + 1) % 3], r[(j + 2) % 3], k);
        if (EDGE) {  // SAME zero-pad at the image boundary, per layer
            const bool rok = (unsigned)(ey0 + 4 * g + j) < uw;
#pragma unroll
            for (int q = 0; q < 4; ++q)
                if (!(rok && ((unsigned)(ex0 + 4 * s + q) < uw))) v[q] = 0.0f;
        }
        *(float4*)(dst + (4 * g + j) * BDT + 4 * s) =
            make_float4(v[0], v[1], v[2], v[3]);
    }
}

template <int BDT>
__device__ __forceinline__ void layer_last_pool(const float* __restrict__ src,
                                                float* __restrict__ out,
                                                int outW, const float k[9],
                                                int s, int g, int oy, int ox) {
    const float* sp = src + (4 * g) * BDT + 4 * s;
    float r[3][8];
    ld8(r[0], sp);
    ld8(r[1], sp + BDT);
    float p[2][2];
#pragma unroll
    for (int j = 0; j < 4; ++j) {
        ld8(r[(j + 2) % 3], sp + (2 + j) * BDT);
        float v[4];
        conv_row(v, r[j % 3], r[(j + 1) % 3], r[(j + 2) % 3], k);
        const int pr = j >> 1;
        float m0 = fmaxf(v[0], v[1]);
        float m1 = fmaxf(v[2], v[3]);
        if ((j & 1) == 0) { p[pr][0] = m0; p[pr][1] = m1; }
        else             { p[pr][0] = fmaxf(p[pr][0], m0);
                           p[pr][1] = fmaxf(p[pr][1], m1); }
    }
    float* op = out + (long)(oy + 2 * g) * outW + (ox + 2 * s);
    *(float2*)op = make_float2(p[0][0], p[0][1]);
    *(float2*)(op + outW) = make_float2(p[1][0], p[1][1]);
}

// ===================== fused K=2 kernel (stages A, B) =====================
// Interior: load 72x72 window (all in-image), ONE barrier, then each of 256
// threads computes l1 (6x6) and l2 (4x4) entirely in registers and stores
// its 2x2 pooled px straight to GMEM. Edge blocks: R8 scalar masked path.
__global__ __launch_bounds__(NT, 3)
void stage2f_kernel(const float* __restrict__ in, int inW,
                    float* __restrict__ out, int outW,
                    const float* __restrict__ w0,
                    const float* __restrict__ w1) {
    constexpr int EXT = 68;
    __shared__ float bufA[BD * BD];
    __shared__ float bufB[BD * BD];
    __shared__ float wts[18];

    const int tid = threadIdx.x;
    if (tid < 18) wts[tid] = (tid < 9) ? w0[tid] : w1[tid - 9];

    const int gx0 = blockIdx.x * 64 - 2;
    const int gy0 = blockIdx.y * 64 - 2;
    const unsigned uw = (unsigned)inW;  // square image
    const bool edge = (gx0 < 0) || (gy0 < 0) ||
                      (gx0 + EXT > inW) || (gy0 + EXT > inW);
    const int ox = blockIdx.x * 32, oy = blockIdx.y * 32;

    if (!edge) {
        // Interior: full 72x72 window is in-image (gx0 even, margins proven)
        // -> unconditional aligned float2 loads (R8 loader).
        if (tid < 288) {
            const int tc = tid % 36;            // float2 column
            const int tr = tid / 36;            // 8 concurrent rows
            const float* gp = in + (long)(gy0 + tr) * inW + gx0 + 2 * tc;
            float* bp = bufA + tr * BD + 2 * tc;
#pragma unroll
            for (int r = 0; r < 9; ++r, gp += 8L * inW, bp += 8 * BD)
                *(float2*)bp = *(const float2*)gp;
        }
        __syncthreads();

        if (tid < 256) {
            const int s = tid & 15;
            const int g = tid >> 4;
            float k1[9], k2[9];
#pragma unroll
            for (int m = 0; m < 9; ++m) { k1[m] = wts[m]; k2[m] = wts[9 + m]; }

            // Thread window: buffer rows 4g..4g+7, cols 4s..4s+7.
            const float* sp = bufA + (4 * g) * BD + 4 * s;
            float r0[8], r1[8], r2[8];   // input row ring
            float a[6], b[6], c[6];      // l1 row ring
            float v[4];

            ld8(r0, sp);
            ld8(r1, sp + BD);
            ld8(r2, sp + 2 * BD);
            l1row6(a, r0, r1, r2, k1);           // l1 t=1
            ld8(r0, sp + 3 * BD);
            l1row6(b, r1, r2, r0, k1);           // t=2
            ld8(r1, sp + 4 * BD);
            l1row6(c, r2, r0, r1, k1);           // t=3
            conv_row(v, a, b, c, k2);            // l2 j=0
            float m0 = fmaxf(v[0], v[1]);
            float m1 = fmaxf(v[2], v[3]);
            ld8(r2, sp + 5 * BD);
            l1row6(a, r0, r1, r2, k1);           // t=4
            conv_row(v, b, c, a, k2);            // j=1
            {
                float* op = out + (long)(oy + 2 * g) * outW + ox + 2 * s;
                *(float2*)op = make_float2(fmaxf(m0, fmaxf(v[0], v[1])),
                                           fmaxf(m1, fmaxf(v[2], v[3])));
            }
            ld8(r0, sp + 6 * BD);
            l1row6(b, r1, r2, r0, k1);           // t=5
            conv_row(v, c, a, b, k2);            // j=2
            m0 = fmaxf(v[0], v[1]);
            m1 = fmaxf(v[2], v[3]);
            ld8(r1, sp + 7 * BD);
            l1row6(c, r2, r0, r1, k1);           // t=6
            conv_row(v, a, b, c, k2);            // j=3
            {
                float* op = out + (long)(oy + 2 * g + 1) * outW + ox + 2 * s;
                *(float2*)op = make_float2(fmaxf(m0, fmaxf(v[0], v[1])),
                                           fmaxf(m1, fmaxf(v[2], v[3])));
            }
        }
        return;
    }

    // ---- edge blocks: R8 masked scalar path (320 >= 289 threads) ----
    for (int i = tid; i < BD * BD; i += NT) {
        int r = i / BD, c = i - r * BD;
        float v = 0.0f;
        if (r < EXT && c < EXT) {
            int gy = gy0 + r, gx = gx0 + c;
            if ((unsigned)gy < uw && (unsigned)gx < uw)
                v = in[(long)gy * inW + gx];
        }
        bufA[i] = v;
        bufB[i] = 0.0f;
    }
    __syncthreads();

    const bool active = tid < 289;
    const int s = tid % 17;
    const int g = tid / 17;
    float k[9];

    if (active) {
#pragma unroll
        for (int m = 0; m < 9; ++m) k[m] = wts[m];
        layer_mid<BD, true>(bufA, bufB, k, s, g, gy0 + 1, gx0 + 1, uw);
    }
    __syncthreads();
    if (active) {
#pragma unroll
        for (int m = 0; m < 9; ++m) k[m] = wts[9 + m];
        layer_mid<BD, true>(bufB, bufA, k, s, g, gy0 + 2, gx0 + 2, uw);
    }
    __syncthreads();
    for (int i = tid; i < 1024; i += NT) {
        int py = i >> 5, px = i & 31;
        const float* p = bufA + (2 * py) * BD + 2 * px;
        float m = fmaxf(fmaxf(p[0], p[1]), fmaxf(p[BD], p[BD + 1]));
        out[(long)(oy + py) * outW + ox + px] = m;
    }
}

// ===================== K=3 stage kernel (C, D) — R12 template =====================
template <int K, int TO, int NTT, int MINCTA>
__global__ __launch_bounds__(NTT, MINCTA)
void stage_kernel(const float* __restrict__ in, int inW,
                  float* __restrict__ out, int outW,
                  const float* __restrict__ w0,
                  const float* __restrict__ w1,
                  const float* __restrict__ w2) {
    constexpr int EXT    = 2 * TO + 2 * K;
    constexpr int STRIPS = (2 * TO + 2 * (K - 1) + 3) / 4;
    constexpr int NACT   = STRIPS * STRIPS;
    constexpr int BDv    = (EXT > 4 * STRIPS + 4) ? EXT : (4 * STRIPS + 4);
    constexpr int BDT    = (BDv + 3) & ~3;

    __shared__ float bufA[BDT * BDT];
    __shared__ float bufB[BDT * BDT];
    __shared__ float wts[27];

    const int tid = threadIdx.x;
    if (tid < K * 9) {
        const float* wp = (tid < 9) ? w0 : ((tid < 18) ? w1 : w2);
        wts[tid] = wp[tid % 9];
    }

    const int gx0 = blockIdx.x * 2 * TO - K;
    const int gy0 = blockIdx.y * 2 * TO - K;
    const unsigned uw = (unsigned)inW;
    const bool edge = (gx0 < 0) || (gy0 < 0) ||
                      (gx0 + EXT > inW) || (gy0 + EXT > inW);

    if (!edge) {
        for (int i = tid; i < BDT * BDT; i += NTT) {
            int r = i / BDT, c = i - r * BDT;
            if (r < EXT && c < EXT)
                bufA[i] = in[(long)(gy0 + r) * inW + (gx0 + c)];
        }
    } else {
        for (int i = tid; i < BDT * BDT; i += NTT) {
            int r = i / BDT, c = i - r * BDT;
            float v = 0.0f;
            if (r < EXT && c < EXT) {
                int gy = gy0 + r, gx = gx0 + c;
                if ((unsigned)gy < uw && (unsigned)gx < uw)
                    v = in[(long)gy * inW + gx];
            }
            bufA[i] = v;
            bufB[i] = 0.0f;
        }
    }
    __syncthreads();

    const bool active = tid < NACT;
    const int s = tid % STRIPS;
    const int g = tid / STRIPS;
    const int ox = blockIdx.x * TO, oy = blockIdx.y * TO;

    float k[9];
    float* src = bufA;
    float* dst = bufB;

#pragma unroll
    for (int c = 0; c < K - 1; ++c) {
        if (active) {
#pragma unroll
            for (int m = 0; m < 9; ++m) k[m] = wts[c * 9 + m];
            if (edge) layer_mid<BDT, true >(src, dst, k, s, g,
                                            gy0 + c + 1, gx0 + c + 1, uw);
            else      layer_mid<BDT, false>(src, dst, k, s, g, 0, 0, uw);
        }
        __syncthreads();
        float* t = src; src = dst; dst = t;
    }

    if (!edge) {
        if (active && s < TO / 2 && g < TO / 2) {
#pragma unroll
            for (int m = 0; m < 9; ++m) k[m] = wts[(K - 1) * 9 + m];
            layer_last_pool<BDT>(src, out, outW, k, s, g, oy, ox);
        }
    } else {
        if (active) {
#pragma unroll
            for (int m = 0; m < 9; ++m) k[m] = wts[(K - 1) * 9 + m];
            layer_mid<BDT, true>(src, dst, k, s, g, gy0 + K, gx0 + K, uw);
        }
        __syncthreads();
        for (int i = tid; i < TO * TO; i += NTT) {
            int py = i / TO, px = i % TO;
            const float* p = dst + (2 * py) * BDT + 2 * px;
            float m = fmaxf(fmaxf(p[0], p[1]), fmaxf(p[BDT], p[BDT + 1]));
            out[(long)(oy + py) * outW + ox + px] = m;
        }
    }
}

extern "C" void kernel_launch(void* const* d_in, const int* in_sizes, int n_in,
                              void* d_out, int out_size) {
    const float* x = (const float*)d_in[0];
    const float* w[10];
    for (int i = 0; i < 10; ++i) w[i] = (const float*)d_in[1 + i];

    float *b0, *b1, *b2;
    cudaGetSymbolAddress((void**)&b0, g_buf0);
    cudaGetSymbolAddress((void**)&b1, g_buf1);
    cudaGetSymbolAddress((void**)&b2, g_buf2);

    float* outp = (float*)d_out;

    // A, B: fused 2-layer register kernel.
    stage2f_kernel<<<dim3(128, 128), NT>>>(x,  8192, b0, 4096, w[0], w[1]);
    stage2f_kernel<<<dim3(64, 64),   NT>>>(b0, 4096, b1, 2048, w[2], w[3]);
    // C: R8 config (TO=32, 320 thr). D: R12 config (TO=16, 128 thr; measured faster).
    stage_kernel<3, 32, 320, 4><<<dim3(32, 32), 320>>>(b1, 2048, b2, 1024, w[4], w[5], w[6]);
    stage_kernel<3, 16, 128, 8><<<dim3(32, 32), 128>>>(b2, 1024, outp, 512, w[7], w[8], w[9]);
}

// round 14
// speedup vs baseline: 1.0929x; 1.0075x over previous
#include <cuda_runtime.h>

// 8192x8192 fp32 input; 10 3x3 SAME convs; 4 2x2 maxpools.
// Stages: [conv,conv,pool] x2 then [conv,conv,conv,pool] x2.
// R14: stages A,B -> persistent software-pipelined fused kernel (interior)
//      + small ring kernel for edge tiles. C,D unchanged from R13.

__device__ float g_buf0[4096u * 4096u];
__device__ float g_buf1[2048u * 2048u];
__device__ float g_buf2[1024u * 1024u];

#define NT 320
#define BD 72

__device__ __forceinline__ void ld8(float* d, const float* p) {
    float4 a = *(const float4*)(p);
    float4 b = *(const float4*)(p + 4);
    d[0] = a.x; d[1] = a.y; d[2] = a.z; d[3] = a.w;
    d[4] = b.x; d[5] = b.y; d[6] = b.z; d[7] = b.w;
}

__device__ __forceinline__ void conv_row(float v[4], const float* r0,
                                         const float* r1, const float* r2,
                                         const float k[9]) {
#pragma unroll
    for (int q = 0; q < 4; ++q) {
        v[q] = r0[q] * k[0] + r0[q + 1] * k[1] + r0[q + 2] * k[2]
             + r1[q] * k[3] + r1[q + 1] * k[4] + r1[q + 2] * k[5]
             + r2[q] * k[6] + r2[q + 1] * k[7] + r2[q + 2] * k[8];
    }
}

__device__ __forceinline__ void l1row6(float o[6], const float* r0,
                                       const float* r1, const float* r2,
                                       const float k[9]) {
#pragma unroll
    for (int q = 0; q < 6; ++q) {
        o[q] = r0[q] * k[0] + r0[q + 1] * k[1] + r0[q + 2] * k[2]
             + r1[q] * k[3] + r1[q + 1] * k[4] + r1[q + 2] * k[5]
             + r2[q] * k[6] + r2[q + 1] * k[7] + r2[q + 2] * k[8];
    }
}

// Fused 2-conv + pool on one interior tile held in `cur` (R13-proven body).
__device__ __forceinline__ void fused_tile(const float* __restrict__ cur,
                                           float* __restrict__ out, int outW,
                                           const float k1[9], const float k2[9],
                                           int s, int g, int oy, int ox) {
    const float* sp = cur + (4 * g) * BD + 4 * s;
    float r0[8], r1[8], r2[8];
    float a[6], b[6], c[6];
    float v[4];

    ld8(r0, sp);
    ld8(r1, sp + BD);
    ld8(r2, sp + 2 * BD);
    l1row6(a, r0, r1, r2, k1);
    ld8(r0, sp + 3 * BD);
    l1row6(b, r1, r2, r0, k1);
    ld8(r1, sp + 4 * BD);
    l1row6(c, r2, r0, r1, k1);
    conv_row(v, a, b, c, k2);
    float m0 = fmaxf(v[0], v[1]);
    float m1 = fmaxf(v[2], v[3]);
    ld8(r2, sp + 5 * BD);
    l1row6(a, r0, r1, r2, k1);
    conv_row(v, b, c, a, k2);
    {
        float* op = out + (long)(oy + 2 * g) * outW + ox + 2 * s;
        *(float2*)op = make_float2(fmaxf(m0, fmaxf(v[0], v[1])),
                                   fmaxf(m1, fmaxf(v[2], v[3])));
    }
    ld8(r0, sp + 6 * BD);
    l1row6(b, r1, r2, r0, k1);
    conv_row(v, c, a, b, k2);
    m0 = fmaxf(v[0], v[1]);
    m1 = fmaxf(v[2], v[3]);
    ld8(r1, sp + 7 * BD);
    l1row6(c, r2, r0, r1, k1);
    conv_row(v, a, b, c, k2);
    {
        float* op = out + (long)(oy + 2 * g + 1) * outW + ox + 2 * s;
        *(float2*)op = make_float2(fmaxf(m0, fmaxf(v[0], v[1])),
                                   fmaxf(m1, fmaxf(v[2], v[3])));
    }
}

// ============ persistent pipelined K=2 kernel (interior tiles) ============
// WT = tiles per dim; interior tiles q in [0, (WT-2)^2), tile (ty,tx) =
// (q/IT+1, q%IT+1). Each CTA strides by gridDim.x. Double-buffered smem:
// LDG for tile t+1 issued before compute of tile t; STS after; 1 barrier.
__global__ __launch_bounds__(NT, 2)
void stage2p_kernel(const float* __restrict__ in, int inW,
                    float* __restrict__ out, int outW,
                    const float* __restrict__ w0,
                    const float* __restrict__ w1, int WT) {
    const int IT  = WT - 2;
    const int NTI = IT * IT;
    __shared__ float bufA[BD * BD];
    __shared__ float bufB[BD * BD];
    __shared__ float wts[18];

    const int tid = threadIdx.x;
    if (tid < 18) wts[tid] = (tid < 9) ? w0[tid] : w1[tid - 9];

    int q = blockIdx.x;
    if (q >= NTI) { return; }  // safety; grid <= NTI in practice

    const int  tc = tid % 36;      // float2 column (loader)
    const int  tr = tid / 36;      // row 0..7 (loader: tid<288)
    const bool loader = tid < 288;
    const int  NC = gridDim.x;

    int ty = q / IT + 1, tx = q % IT + 1;

    float2 x[9];
    // prologue: load tile q into bufA
    if (loader) {
        const float* gp = in + ((long)ty * 64 - 2 + tr) * inW
                             + (long)tx * 64 - 2 + 2 * tc;
#pragma unroll
        for (int r = 0; r < 9; ++r)
            x[r] = *(const float2*)(gp + (long)8 * r * inW);
        float* bp = bufA + tr * BD + 2 * tc;
#pragma unroll
        for (int r = 0; r < 9; ++r) *(float2*)(bp + 8 * r * BD) = x[r];
    }
    __syncthreads();

    float k1[9], k2[9];
#pragma unroll
    for (int m = 0; m < 9; ++m) { k1[m] = wts[m]; k2[m] = wts[9 + m]; }

    float* cur = bufA;
    float* nxt = bufB;
    const int s = tid & 15;
    const int g = (tid < 256) ? (tid >> 4) : 0;

    while (true) {
        const int  qn = q + NC;
        const bool hasnext = qn < NTI;

        // issue LDGs for the next tile (fire-and-forget; consumed at STS)
        if (hasnext && loader) {
            int tyn = qn / IT + 1, txn = qn % IT + 1;
            const float* gp = in + ((long)tyn * 64 - 2 + tr) * inW
                                 + (long)txn * 64 - 2 + 2 * tc;
#pragma unroll
            for (int r = 0; r < 9; ++r)
                x[r] = *(const float2*)(gp + (long)8 * r * inW);
        }

        // compute current tile (256 threads) — hides the LDG latency
        if (tid < 256)
            fused_tile(cur, out, outW, k1, k2, s, g, ty * 32, tx * 32);

        if (!hasnext) break;

        // stage next tile into the other buffer
        if (loader) {
            float* bp = nxt + tr * BD + 2 * tc;
#pragma unroll
            for (int r = 0; r < 9; ++r) *(float2*)(bp + 8 * r * BD) = x[r];
        }
        __syncthreads();

        q = qn; ty = q / IT + 1; tx = q % IT + 1;
        float* t = cur; cur = nxt; nxt = t;
    }
}

// ============ edge-ring K=2 kernel (R13 edge path, ring-mapped) ============
template <bool EDGE>
__device__ __forceinline__ void layer_mid2(const float* __restrict__ src,
                                           float* __restrict__ dst,
                                           const float k[9], int s, int g,
                                           int ey0, int ex0, unsigned uw) {
    const float* sp = src + (4 * g) * BD + 4 * s;
    float r[3][8];
    ld8(r[0], sp);
    ld8(r[1], sp + BD);
#pragma unroll
    for (int j = 0; j < 4; ++j) {
        ld8(r[(j + 2) % 3], sp + (2 + j) * BD);
        float v[4];
        conv_row(v, r[j % 3], r[(j + 1) % 3], r[(j + 2) % 3], k);
        if (EDGE) {
            const bool rok = (unsigned)(ey0 + 4 * g + j) < uw;
#pragma unroll
            for (int q = 0; q < 4; ++q)
                if (!(rok && ((unsigned)(ex0 + 4 * s + q) < uw))) v[q] = 0.0f;
        }
        *(float4*)(dst + (4 * g + j) * BD + 4 * s) =
            make_float4(v[0], v[1], v[2], v[3]);
    }
}

__global__ __launch_bounds__(NT, 3)
void stage2e_kernel(const float* __restrict__ in, int inW,
                    float* __restrict__ out, int outW,
                    const float* __restrict__ w0,
                    const float* __restrict__ w1, int WT) {
    constexpr int EXT = 68;
    __shared__ float bufA[BD * BD];
    __shared__ float bufB[BD * BD];
    __shared__ float wts[18];

    const int tid = threadIdx.x;
    if (tid < 18) wts[tid] = (tid < 9) ? w0[tid] : w1[tid - 9];

    // ring mapping: border tiles only
    const int b = blockIdx.x;
    int tx, ty;
    if (b < WT)            { tx = b;                ty = 0; }
    else if (b < 2 * WT)   { tx = b - WT;           ty = WT - 1; }
    else if (b < 3 * WT - 2) { tx = 0;              ty = b - 2 * WT + 1; }
    else                   { tx = WT - 1;           ty = b - (3 * WT - 2) + 1; }

    const int gx0 = tx * 64 - 2;
    const int gy0 = ty * 64 - 2;
    const unsigned uw = (unsigned)inW;
    const int ox = tx * 32, oy = ty * 32;

    for (int i = tid; i < BD * BD; i += NT) {
        int r = i / BD, c = i - r * BD;
        float v = 0.0f;
        if (r < EXT && c < EXT) {
            int gy = gy0 + r, gx = gx0 + c;
            if ((unsigned)gy < uw && (unsigned)gx < uw)
                v = in[(long)gy * inW + gx];
        }
        bufA[i] = v;
        bufB[i] = 0.0f;
    }
    __syncthreads();

    const bool active = tid < 289;
    const int s = tid % 17;
    const int g = tid / 17;
    float k[9];

    if (active) {
#pragma unroll
        for (int m = 0; m < 9; ++m) k[m] = wts[m];
        layer_mid2<true>(bufA, bufB, k, s, g, gy0 + 1, gx0 + 1, uw);
    }
    __syncthreads();
    if (active) {
#pragma unroll
        for (int m = 0; m < 9; ++m) k[m] = wts[9 + m];
        layer_mid2<true>(bufB, bufA, k, s, g, gy0 + 2, gx0 + 2, uw);
    }
    __syncthreads();
    for (int i = tid; i < 1024; i += NT) {
        int py = i >> 5, px = i & 31;
        const float* p = bufA + (2 * py) * BD + 2 * px;
        float m = fmaxf(fmaxf(p[0], p[1]), fmaxf(p[BD], p[BD + 1]));
        out[(long)(oy + py) * outW + ox + px] = m;
    }
}

// ============ K=3 stage kernel (C, D) — unchanged R13 template ============
template <int BDT>
__device__ __forceinline__ void layer_last_pool3(const float* __restrict__ src,
                                                 float* __restrict__ out,
                                                 int outW, const float k[9],
                                                 int s, int g, int oy, int ox) {
    const float* sp = src + (4 * g) * BDT + 4 * s;
    float r[3][8];
    ld8(r[0], sp);
    ld8(r[1], sp + BDT);
    float p[2][2];
#pragma unroll
    for (int j = 0; j < 4; ++j) {
        ld8(r[(j + 2) % 3], sp + (2 + j) * BDT);
        float v[4];
        conv_row(v, r[j % 3], r[(j + 1) % 3], r[(j + 2) % 3], k);
        const int pr = j >> 1;
        float m0 = fmaxf(v[0], v[1]);
        float m1 = fmaxf(v[2], v[3]);
        if ((j & 1) == 0) { p[pr][0] = m0; p[pr][1] = m1; }
        else             { p[pr][0] = fmaxf(p[pr][0], m0);
                           p[pr][1] = fmaxf(p[pr][1], m1); }
    }
    float* op = out + (long)(oy + 2 * g) * outW + (ox + 2 * s);
    *(float2*)op = make_float2(p[0][0], p[0][1]);
    *(float2*)(op + outW) = make_float2(p[1][0], p[1][1]);
}

template <int BDT, bool EDGE>
__device__ __forceinline__ void layer_mid3(const float* __restrict__ src,
                                           float* __restrict__ dst,
                                           const float k[9], int s, int g,
                                           int ey0, int ex0, unsigned uw) {
    const float* sp = src + (4 * g) * BDT + 4 * s;
    float r[3][8];
    ld8(r[0], sp);
    ld8(r[1], sp + BDT);
#pragma unroll
    for (int j = 0; j < 4; ++j) {
        ld8(r[(j + 2) % 3], sp + (2 + j) * BDT);
        float v[4];
        conv_row(v, r[j % 3], r[(j + 1) % 3], r[(j + 2) % 3], k);
        if (EDGE) {
            const bool rok = (unsigned)(ey0 + 4 * g + j) < uw;
#pragma unroll
            for (int q = 0; q < 4; ++q)
                if (!(rok && ((unsigned)(ex0 + 4 * s + q) < uw))) v[q] = 0.0f;
        }
        *(float4*)(dst + (4 * g + j) * BDT + 4 * s) =
            make_float4(v[0], v[1], v[2], v[3]);
    }
}

template <int K, int TO, int NTT, int MINCTA>
__global__ __launch_bounds__(NTT, MINCTA)
void stage_kernel(const float* __restrict__ in, int inW,
                  float* __restrict__ out, int outW,
                  const float* __restrict__ w0,
                  const float* __restrict__ w1,
                  const float* __restrict__ w2) {
    constexpr int EXT    = 2 * TO + 2 * K;
    constexpr int STRIPS = (2 * TO + 2 * (K - 1) + 3) / 4;
    constexpr int NACT   = STRIPS * STRIPS;
    constexpr int BDv    = (EXT > 4 * STRIPS + 4) ? EXT : (4 * STRIPS + 4);
    constexpr int BDT    = (BDv + 3) & ~3;

    __shared__ float bufA[BDT * BDT];
    __shared__ float bufB[BDT * BDT];
    __shared__ float wts[27];

    const int tid = threadIdx.x;
    if (tid < K * 9) {
        const float* wp = (tid < 9) ? w0 : ((tid < 18) ? w1 : w2);
        wts[tid] = wp[tid % 9];
    }

    const int gx0 = blockIdx.x * 2 * TO - K;
    const int gy0 = blockIdx.y * 2 * TO - K;
    const unsigned uw = (unsigned)inW;
    const bool edge = (gx0 < 0) || (gy0 < 0) ||
                      (gx0 + EXT > inW) || (gy0 + EXT > inW);

    if (!edge) {
        for (int i = tid; i < BDT * BDT; i += NTT) {
            int r = i / BDT, c = i - r * BDT;
            if (r < EXT && c < EXT)
                bufA[i] = in[(long)(gy0 + r) * inW + (gx0 + c)];
        }
    } else {
        for (int i = tid; i < BDT * BDT; i += NTT) {
            int r = i / BDT, c = i - r * BDT;
            float v = 0.0f;
            if (r < EXT && c < EXT) {
                int gy = gy0 + r, gx = gx0 + c;
                if ((unsigned)gy < uw && (unsigned)gx < uw)
                    v = in[(long)gy * inW + gx];
            }
            bufA[i] = v;
            bufB[i] = 0.0f;
        }
    }
    __syncthreads();

    const bool active = tid < NACT;
    const int s = tid % STRIPS;
    const int g = tid / STRIPS;
    const int ox = blockIdx.x * TO, oy = blockIdx.y * TO;

    float k[9];
    float* src = bufA;
    float* dst = bufB;

#pragma unroll
    for (int c = 0; c < K - 1; ++c) {
        if (active) {
#pragma unroll
            for (int m = 0; m < 9; ++m) k[m] = wts[c * 9 + m];
            if (edge) layer_mid3<BDT, true >(src, dst, k, s, g,
                                             gy0 + c + 1, gx0 + c + 1, uw);
            else      layer_mid3<BDT, false>(src, dst, k, s, g, 0, 0, uw);
        }
        __syncthreads();
        float* t = src; src = dst; dst = t;
    }

    if (!edge) {
        if (active && s < TO / 2 && g < TO / 2) {
#pragma unroll
            for (int m = 0; m < 9; ++m) k[m] = wts[(K - 1) * 9 + m];
            layer_last_pool3<BDT>(src, out, outW, k, s, g, oy, ox);
        }
    } else {
        if (active) {
#pragma unroll
            for (int m = 0; m < 9; ++m) k[m] = wts[(K - 1) * 9 + m];
            layer_mid3<BDT, true>(src, dst, k, s, g, gy0 + K, gx0 + K, uw);
        }
        __syncthreads();
        for (int i = tid; i < TO * TO; i += NTT) {
            int py = i / TO, px = i % TO;
            const float* p = dst + (2 * py) * BDT + 2 * px;
            float m = fmaxf(fmaxf(p[0], p[1]), fmaxf(p[BDT], p[BDT + 1]));
            out[(long)(oy + py) * outW + ox + px] = m;
        }
    }
}

extern "C" void kernel_launch(void* const* d_in, const int* in_sizes, int n_in,
                              void* d_out, int out_size) {
    const float* x = (const float*)d_in[0];
    const float* w[10];
    for (int i = 0; i < 10; ++i) w[i] = (const float*)d_in[1 + i];

    float *b0, *b1, *b2;
    cudaGetSymbolAddress((void**)&b0, g_buf0);
    cudaGetSymbolAddress((void**)&b1, g_buf1);
    cudaGetSymbolAddress((void**)&b2, g_buf2);

    float* outp = (float*)d_out;

    // Stage A: edge ring (508 tiles) + persistent interior (15876 tiles).
    stage2e_kernel<<<4 * 128 - 4, NT>>>(x, 8192, b0, 4096, w[0], w[1], 128);
    stage2p_kernel<<<296,         NT>>>(x, 8192, b0, 4096, w[0], w[1], 128);
    // Stage B: edge ring (252) + persistent interior (3844).
    stage2e_kernel<<<4 * 64 - 4,  NT>>>(b0, 4096, b1, 2048, w[2], w[3], 64);
    stage2p_kernel<<<296,         NT>>>(b0, 4096, b1, 2048, w[2], w[3], 64);
    // Stages C, D: unchanged from R13.
    stage_kernel<3, 32, 320, 4><<<dim3(32, 32), 320>>>(b1, 2048, b2, 1024, w[4], w[5], w[6]);
    stage_kernel<3, 16, 128, 8><<<dim3(32, 32), 128>>>(b2, 1024, outp, 512, w[7], w[8], w[9]);
}

// round 15
// speedup vs baseline: 1.1183x; 1.0233x over previous
#include <cuda_runtime.h>
#include <cstdint>

// 8192x8192 fp32 input; 10 3x3 SAME convs; 4 2x2 maxpools.
// R15 = R14 persistent pipeline + f32x2 layer-1 + cp.async staging.
//      Edge rings and stages C,D unchanged from R14.

__device__ float g_buf0[4096u * 4096u];
__device__ float g_buf1[2048u * 2048u];
__device__ float g_buf2[1024u * 1024u];

#define NT  320   // edge + K=3 kernels
#define NTP 288   // persistent kernel (all 288 load, 256 compute)
#define BD  72

// ---- f32x2 primitives ----
__device__ __forceinline__ float2 pack2(float x, float y) {
    float2 r;
    asm("mov.b64 %0, {%1, %2};"
        : "=l"(*(unsigned long long*)&r) : "f"(x), "f"(y));
    return r;
}
__device__ __forceinline__ float2 ffma2(float2 a, float2 b, float2 c) {
    float2 d;
    asm("fma.rn.f32x2 %0, %1, %2, %3;"
        : "=l"(*(unsigned long long*)&d)
        : "l"(*(unsigned long long*)&a),
          "l"(*(unsigned long long*)&b),
          "l"(*(unsigned long long*)&c));
    return d;
}
__device__ __forceinline__ float2 fmul2(float2 a, float2 b) {
    float2 d;
    asm("mul.rn.f32x2 %0, %1, %2;"
        : "=l"(*(unsigned long long*)&d)
        : "l"(*(unsigned long long*)&a),
          "l"(*(unsigned long long*)&b));
    return d;
}

// ---- cp.async ----
__device__ __forceinline__ void cp_async8(uint32_t dst, const float* src) {
    asm volatile("cp.async.ca.shared.global [%0], [%1], 8;"
                 :: "r"(dst), "l"(src));
}
__device__ __forceinline__ void cp_commit() {
    asm volatile("cp.async.commit_group;");
}
__device__ __forceinline__ void cp_wait0() {
    asm volatile("cp.async.wait_group 0;" ::: "memory");
}

__device__ __forceinline__ void ld8(float* d, const float* p) {
    float4 a = *(const float4*)(p);
    float4 b = *(const float4*)(p + 4);
    d[0] = a.x; d[1] = a.y; d[2] = a.z; d[3] = a.w;
    d[4] = b.x; d[5] = b.y; d[6] = b.z; d[7] = b.w;
}

__device__ __forceinline__ void conv_row(float v[4], const float* r0,
                                         const float* r1, const float* r2,
                                         const float k[9]) {
#pragma unroll
    for (int q = 0; q < 4; ++q) {
        v[q] = r0[q] * k[0] + r0[q + 1] * k[1] + r0[q + 2] * k[2]
             + r1[q] * k[3] + r1[q + 1] * k[4] + r1[q + 2] * k[5]
             + r2[q] * k[6] + r2[q + 1] * k[7] + r2[q + 2] * k[8];
    }
}

// ---- 8-float row as f32x2 operand set (natural pairs + crossings) ----
struct Row2 {
    float2 p0, p1, p2, p3;  // (0,1)(2,3)(4,5)(6,7)
    float2 q0, q1, q2;      // (1,2)(3,4)(5,6)
};

__device__ __forceinline__ void ld_row2(Row2& r, const float* sp) {
    float4 A = *(const float4*)sp;
    float4 B = *(const float4*)(sp + 4);
    r.p0 = make_float2(A.x, A.y);
    r.p1 = make_float2(A.z, A.w);
    r.p2 = make_float2(B.x, B.y);
    r.p3 = make_float2(B.z, B.w);
    r.q0 = pack2(A.y, A.z);
    r.q1 = pack2(A.w, B.x);
    r.q2 = pack2(B.y, B.z);
}

// layer-1, 6 outputs as 3 float2: o[j] covers cols (2j, 2j+1).
__device__ __forceinline__ void l1row6_v2(float2 o[3], const Row2& r0,
                                          const Row2& r1, const Row2& r2,
                                          const float2 k[9]) {
    o[0] = fmul2(r0.p0, k[0]);
    o[0] = ffma2(r0.q0, k[1], o[0]);
    o[0] = ffma2(r0.p1, k[2], o[0]);
    o[0] = ffma2(r1.p0, k[3], o[0]);
    o[0] = ffma2(r1.q0, k[4], o[0]);
    o[0] = ffma2(r1.p1, k[5], o[0]);
    o[0] = ffma2(r2.p0, k[6], o[0]);
    o[0] = ffma2(r2.q0, k[7], o[0]);
    o[0] = ffma2(r2.p1, k[8], o[0]);

    o[1] = fmul2(r0.p1, k[0]);
    o[1] = ffma2(r0.q1, k[1], o[1]);
    o[1] = ffma2(r0.p2, k[2], o[1]);
    o[1] = ffma2(r1.p1, k[3], o[1]);
    o[1] = ffma2(r1.q1, k[4], o[1]);
    o[1] = ffma2(r1.p2, k[5], o[1]);
    o[1] = ffma2(r2.p1, k[6], o[1]);
    o[1] = ffma2(r2.q1, k[7], o[1]);
    o[1] = ffma2(r2.p2, k[8], o[1]);

    o[2] = fmul2(r0.p2, k[0]);
    o[2] = ffma2(r0.q2, k[1], o[2]);
    o[2] = ffma2(r0.p3, k[2], o[2]);
    o[2] = ffma2(r1.p2, k[3], o[2]);
    o[2] = ffma2(r1.q2, k[4], o[2]);
    o[2] = ffma2(r1.p3, k[5], o[2]);
    o[2] = ffma2(r2.p2, k[6], o[2]);
    o[2] = ffma2(r2.q2, k[7], o[2]);
    o[2] = ffma2(r2.p3, k[8], o[2]);
}

// Fused 2-conv + pool on one interior tile (f32x2 layer-1, scalar layer-2).
__device__ __forceinline__ void fused_tile2(const float* __restrict__ cur,
                                            float* __restrict__ out, int outW,
                                            const float2 k1[9], const float k2[9],
                                            int s, int g, int oy, int ox) {
    const float* sp = cur + (4 * g) * BD + 4 * s;
    Row2 r0, r1, r2;
    float2 a[3], b[3], c[3];
    const float* af = (const float*)a;
    const float* bf = (const float*)b;
    const float* cf = (const float*)c;
    float v[4];

    ld_row2(r0, sp);
    ld_row2(r1, sp + BD);
    ld_row2(r2, sp + 2 * BD);
    l1row6_v2(a, r0, r1, r2, k1);
    ld_row2(r0, sp + 3 * BD);
    l1row6_v2(b, r1, r2, r0, k1);
    ld_row2(r1, sp + 4 * BD);
    l1row6_v2(c, r2, r0, r1, k1);
    conv_row(v, af, bf, cf, k2);
    float m0 = fmaxf(v[0], v[1]);
    float m1 = fmaxf(v[2], v[3]);
    ld_row2(r2, sp + 5 * BD);
    l1row6_v2(a, r0, r1, r2, k1);
    conv_row(v, bf, cf, af, k2);
    {
        float* op = out + (long)(oy + 2 * g) * outW + ox + 2 * s;
        *(float2*)op = make_float2(fmaxf(m0, fmaxf(v[0], v[1])),
                                   fmaxf(m1, fmaxf(v[2], v[3])));
    }
    ld_row2(r0, sp + 6 * BD);
    l1row6_v2(b, r1, r2, r0, k1);
    conv_row(v, cf, af, bf, k2);
    m0 = fmaxf(v[0], v[1]);
    m1 = fmaxf(v[2], v[3]);
    ld_row2(r1, sp + 7 * BD);
    l1row6_v2(c, r2, r0, r1, k1);
    conv_row(v, af, bf, cf, k2);
    {
        float* op = out + (long)(oy + 2 * g + 1) * outW + ox + 2 * s;
        *(float2*)op = make_float2(fmaxf(m0, fmaxf(v[0], v[1])),
                                   fmaxf(m1, fmaxf(v[2], v[3])));
    }
}

// ============ persistent pipelined K=2 kernel (interior tiles) ============
__global__ __launch_bounds__(NTP, 2)
void stage2p_kernel(const float* __restrict__ in, int inW,
                    float* __restrict__ out, int outW,
                    const float* __restrict__ w0,
                    const float* __restrict__ w1, int WT) {
    const int IT  = WT - 2;
    const int NTI = IT * IT;
    __shared__ float bufA[BD * BD];
    __shared__ float bufB[BD * BD];
    __shared__ float wts[18];

    const int tid = threadIdx.x;
    if (tid < 18) wts[tid] = (tid < 9) ? w0[tid] : w1[tid - 9];

    int q = blockIdx.x;
    if (q >= NTI) return;

    const int tc = tid % 36;  // float2 column
    const int tr = tid / 36;  // row 0..7
    const int NC = gridDim.x;

    int ty = q / IT + 1, tx = q % IT + 1;

    const uint32_t sA = (uint32_t)__cvta_generic_to_shared(bufA);
    const uint32_t sB = (uint32_t)__cvta_generic_to_shared(bufB);

    // prologue: stage tile q into bufA via cp.async
    {
        const float* gp = in + ((long)ty * 64 - 2 + tr) * inW
                             + (long)tx * 64 - 2 + 2 * tc;
        uint32_t dp = sA + (tr * BD + 2 * tc) * 4;
#pragma unroll
        for (int r = 0; r < 9; ++r)
            cp_async8(dp + r * 8 * BD * 4, gp + (long)8 * r * inW);
        cp_commit();
    }
    cp_wait0();
    __syncthreads();

    float2 k1[9];
    float  k2[9];
#pragma unroll
    for (int m = 0; m < 9; ++m) {
        float kv = wts[m];
        k1[m] = pack2(kv, kv);
        k2[m] = wts[9 + m];
    }

    const float* cur = bufA;
    uint32_t     nxt = sB;
    const int s = tid & 15;
    const int g = (tid < 256) ? (tid >> 4) : 0;

    while (true) {
        const int  qn = q + NC;
        const bool hasnext = qn < NTI;

        // stage next tile asynchronously (no regs held, no STS)
        if (hasnext) {
            int tyn = qn / IT + 1, txn = qn % IT + 1;
            const float* gp = in + ((long)tyn * 64 - 2 + tr) * inW
                                 + (long)txn * 64 - 2 + 2 * tc;
            uint32_t dp = nxt + (tr * BD + 2 * tc) * 4;
#pragma unroll
            for (int r = 0; r < 9; ++r)
                cp_async8(dp + r * 8 * BD * 4, gp + (long)8 * r * inW);
            cp_commit();
        }

        // compute current tile — hides the async loads
        if (tid < 256)
            fused_tile2(cur, out, outW, k1, k2, s, g, ty * 32, tx * 32);

        if (!hasnext) break;

        cp_wait0();
        __syncthreads();

        q = qn; ty = q / IT + 1; tx = q % IT + 1;
        const float* t = cur;
        cur = (cur == bufA) ? bufB : bufA;
        nxt = (t == bufA) ? sA : sB;
    }
}

// ============ edge-ring K=2 kernel (unchanged R14) ============
template <bool EDGE>
__device__ __forceinline__ void layer_mid2(const float* __restrict__ src,
                                           float* __restrict__ dst,
                                           const float k[9], int s, int g,
                                           int ey0, int ex0, unsigned uw) {
    const float* sp = src + (4 * g) * BD + 4 * s;
    float r[3][8];
    ld8(r[0], sp);
    ld8(r[1], sp + BD);
#pragma unroll
    for (int j = 0; j < 4; ++j) {
        ld8(r[(j + 2) % 3], sp + (2 + j) * BD);
        float v[4];
        conv_row(v, r[j % 3], r[(j + 1) % 3], r[(j + 2) % 3], k);
        if (EDGE) {
            const bool rok = (unsigned)(ey0 + 4 * g + j) < uw;
#pragma unroll
            for (int q = 0; q < 4; ++q)
                if (!(rok && ((unsigned)(ex0 + 4 * s + q) < uw))) v[q] = 0.0f;
        }
        *(float4*)(dst + (4 * g + j) * BD + 4 * s) =
            make_float4(v[0], v[1], v[2], v[3]);
    }
}

__global__ __launch_bounds__(NT, 3)
void stage2e_kernel(const float* __restrict__ in, int inW,
                    float* __restrict__ out, int outW,
                    const float* __restrict__ w0,
                    const float* __restrict__ w1, int WT) {
    constexpr int EXT = 68;
    __shared__ float bufA[BD * BD];
    __shared__ float bufB[BD * BD];
    __shared__ float wts[18];

    const int tid = threadIdx.x;
    if (tid < 18) wts[tid] = (tid < 9) ? w0[tid] : w1[tid - 9];

    const int b = blockIdx.x;
    int tx, ty;
    if (b < WT)              { tx = b;        ty = 0; }
    else if (b < 2 * WT)     { tx = b - WT;   ty = WT - 1; }
    else if (b < 3 * WT - 2) { tx = 0;        ty = b - 2 * WT + 1; }
    else                     { tx = WT - 1;   ty = b - (3 * WT - 2) + 1; }

    const int gx0 = tx * 64 - 2;
    const int gy0 = ty * 64 - 2;
    const unsigned uw = (unsigned)inW;
    const int ox = tx * 32, oy = ty * 32;

    for (int i = tid; i < BD * BD; i += NT) {
        int r = i / BD, c = i - r * BD;
        float v = 0.0f;
        if (r < EXT && c < EXT) {
            int gy = gy0 + r, gx = gx0 + c;
            if ((unsigned)gy < uw && (unsigned)gx < uw)
                v = in[(long)gy * inW + gx];
        }
        bufA[i] = v;
        bufB[i] = 0.0f;
    }
    __syncthreads();

    const bool active = tid < 289;
    const int s = tid % 17;
    const int g = tid / 17;
    float k[9];

    if (active) {
#pragma unroll
        for (int m = 0; m < 9; ++m) k[m] = wts[m];
        layer_mid2<true>(bufA, bufB, k, s, g, gy0 + 1, gx0 + 1, uw);
    }
    __syncthreads();
    if (active) {
#pragma unroll
        for (int m = 0; m < 9; ++m) k[m] = wts[9 + m];
        layer_mid2<true>(bufB, bufA, k, s, g, gy0 + 2, gx0 + 2, uw);
    }
    __syncthreads();
    for (int i = tid; i < 1024; i += NT) {
        int py = i >> 5, px = i & 31;
        const float* p = bufA + (2 * py) * BD + 2 * px;
        float m = fmaxf(fmaxf(p[0], p[1]), fmaxf(p[BD], p[BD + 1]));
        out[(long)(oy + py) * outW + ox + px] = m;
    }
}

// ============ K=3 stage kernel (C, D) — unchanged ============
template <int BDT>
__device__ __forceinline__ void layer_last_pool3(const float* __restrict__ src,
                                                 float* __restrict__ out,
                                                 int outW, const float k[9],
                                                 int s, int g, int oy, int ox) {
    const float* sp = src + (4 * g) * BDT + 4 * s;
    float r[3][8];
    ld8(r[0], sp);
    ld8(r[1], sp + BDT);
    float p[2][2];
#pragma unroll
    for (int j = 0; j < 4; ++j) {
        ld8(r[(j + 2) % 3], sp + (2 + j) * BDT);
        float v[4];
        conv_row(v, r[j % 3], r[(j + 1) % 3], r[(j + 2) % 3], k);
        const int pr = j >> 1;
        float m0 = fmaxf(v[0], v[1]);
        float m1 = fmaxf(v[2], v[3]);
        if ((j & 1) == 0) { p[pr][0] = m0; p[pr][1] = m1; }
        else             { p[pr][0] = fmaxf(p[pr][0], m0);
                           p[pr][1] = fmaxf(p[pr][1], m1); }
    }
    float* op = out + (long)(oy + 2 * g) * outW + (ox + 2 * s);
    *(float2*)op = make_float2(p[0][0], p[0][1]);
    *(float2*)(op + outW) = make_float2(p[1][0], p[1][1]);
}

template <int BDT, bool EDGE>
__device__ __forceinline__ void layer_mid3(const float* __restrict__ src,
                                           float* __restrict__ dst,
                                           const float k[9], int s, int g,
                                           int ey0, int ex0, unsigned uw) {
    const float* sp = src + (4 * g) * BDT + 4 * s;
    float r[3][8];
    ld8(r[0], sp);
    ld8(r[1], sp + BDT);
#pragma unroll
    for (int j = 0; j < 4; ++j) {
        ld8(r[(j + 2) % 3], sp + (2 + j) * BDT);
        float v[4];
        conv_row(v, r[j % 3], r[(j + 1) % 3], r[(j + 2) % 3], k);
        if (EDGE) {
            const bool rok = (unsigned)(ey0 + 4 * g + j) < uw;
#pragma unroll
            for (int q = 0; q < 4; ++q)
                if (!(rok && ((unsigned)(ex0 + 4 * s + q) < uw))) v[q] = 0.0f;
        }
        *(float4*)(dst + (4 * g + j) * BDT + 4 * s) =
            make_float4(v[0], v[1], v[2], v[3]);
    }
}

template <int K, int TO, int NTT, int MINCTA>
__global__ __launch_bounds__(NTT, MINCTA)
void stage_kernel(const float* __restrict__ in, int inW,
                  float* __restrict__ out, int outW,
                  const float* __restrict__ w0,
                  const float* __restrict__ w1,
                  const float* __restrict__ w2) {
    constexpr int EXT    = 2 * TO + 2 * K;
    constexpr int STRIPS = (2 * TO + 2 * (K - 1) + 3) / 4;
    constexpr int NACT   = STRIPS * STRIPS;
    constexpr int BDv    = (EXT > 4 * STRIPS + 4) ? EXT : (4 * STRIPS + 4);
    constexpr int BDT    = (BDv + 3) & ~3;

    __shared__ float bufA[BDT * BDT];
    __shared__ float bufB[BDT * BDT];
    __shared__ float wts[27];

    const int tid = threadIdx.x;
    if (tid < K * 9) {
        const float* wp = (tid < 9) ? w0 : ((tid < 18) ? w1 : w2);
        wts[tid] = wp[tid % 9];
    }

    const int gx0 = blockIdx.x * 2 * TO - K;
    const int gy0 = blockIdx.y * 2 * TO - K;
    const unsigned uw = (unsigned)inW;
    const bool edge = (gx0 < 0) || (gy0 < 0) ||
                      (gx0 + EXT > inW) || (gy0 + EXT > inW);

    if (!edge) {
        for (int i = tid; i < BDT * BDT; i += NTT) {
            int r = i / BDT, c = i - r * BDT;
            if (r < EXT && c < EXT)
                bufA[i] = in[(long)(gy0 + r) * inW + (gx0 + c)];
        }
    } else {
        for (int i = tid; i < BDT * BDT; i += NTT) {
            int r = i / BDT, c = i - r * BDT;
            float v = 0.0f;
            if (r < EXT && c < EXT) {
                int gy = gy0 + r, gx = gx0 + c;
                if ((unsigned)gy < uw && (unsigned)gx < uw)
                    v = in[(long)gy * inW + gx];
            }
            bufA[i] = v;
            bufB[i] = 0.0f;
        }
    }
    __syncthreads();

    const bool active = tid < NACT;
    const int s = tid % STRIPS;
    const int g = tid / STRIPS;
    const int ox = blockIdx.x * TO, oy = blockIdx.y * TO;

    float k[9];
    float* src = bufA;
    float* dst = bufB;

#pragma unroll
    for (int c = 0; c < K - 1; ++c) {
        if (active) {
#pragma unroll
            for (int m = 0; m < 9; ++m) k[m] = wts[c * 9 + m];
            if (edge) layer_mid3<BDT, true >(src, dst, k, s, g,
                                             gy0 + c + 1, gx0 + c + 1, uw);
            else      layer_mid3<BDT, false>(src, dst, k, s, g, 0, 0, uw);
        }
        __syncthreads();
        float* t = src; src = dst; dst = t;
    }

    if (!edge) {
        if (active && s < TO / 2 && g < TO / 2) {
#pragma unroll
            for (int m = 0; m < 9; ++m) k[m] = wts[(K - 1) * 9 + m];
            layer_last_pool3<BDT>(src, out, outW, k, s, g, oy, ox);
        }
    } else {
        if (active) {
#pragma unroll
            for (int m = 0; m < 9; ++m) k[m] = wts[(K - 1) * 9 + m];
            layer_mid3<BDT, true>(src, dst, k, s, g, gy0 + K, gx0 + K, uw);
        }
        __syncthreads();
        for (int i = tid; i < TO * TO; i += NTT) {
            int py = i / TO, px = i % TO;
            const float* p = dst + (2 * py) * BDT + 2 * px;
            float m = fmaxf(fmaxf(p[0], p[1]), fmaxf(p[BDT], p[BDT + 1]));
            out[(long)(oy + py) * outW + ox + px] = m;
        }
    }
}

extern "C" void kernel_launch(void* const* d_in, const int* in_sizes, int n_in,
                              void* d_out, int out_size) {
    const float* x = (const float*)d_in[0];
    const float* w[10];
    for (int i = 0; i < 10; ++i) w[i] = (const float*)d_in[1 + i];

    float *b0, *b1, *b2;
    cudaGetSymbolAddress((void**)&b0, g_buf0);
    cudaGetSymbolAddress((void**)&b1, g_buf1);
    cudaGetSymbolAddress((void**)&b2, g_buf2);

    float* outp = (float*)d_out;

    stage2e_kernel<<<4 * 128 - 4, NT>>>(x, 8192, b0, 4096, w[0], w[1], 128);
    stage2p_kernel<<<296,        NTP>>>(x, 8192, b0, 4096, w[0], w[1], 128);
    stage2e_kernel<<<4 * 64 - 4,  NT>>>(b0, 4096, b1, 2048, w[2], w[3], 64);
    stage2p_kernel<<<296,        NTP>>>(b0, 4096, b1, 2048, w[2], w[3], 64);
    stage_kernel<3, 32, 320, 4><<<dim3(32, 32), 320>>>(b1, 2048, b2, 1024, w[4], w[5], w[6]);
    stage_kernel<3, 16, 128, 8><<<dim3(32, 32), 128>>>(b2, 1024, outp, 512, w[7], w[8], w[9]);
}

// round 16
// speedup vs baseline: 1.1632x; 1.0401x over previous
#include <cuda_runtime.h>
#include <cstdint>

// 8192x8192 fp32 input; 10 3x3 SAME convs; 4 2x2 maxpools.
// R16 = R15 + persistent kernel reg-diet (no stored crossing pairs,
//       compile-time WT) -> 3 CTAs/SM; grid 296->444. Rest unchanged.

__device__ float g_buf0[4096u * 4096u];
__device__ float g_buf1[2048u * 2048u];
__device__ float g_buf2[1024u * 1024u];

#define NT  320   // edge + K=3 kernels
#define NTP 288   // persistent kernel
#define BD  72

// ---- f32x2 primitives ----
__device__ __forceinline__ float2 pack2(float x, float y) {
    float2 r;
    asm("mov.b64 %0, {%1, %2};"
        : "=l"(*(unsigned long long*)&r) : "f"(x), "f"(y));
    return r;
}
__device__ __forceinline__ float2 ffma2(float2 a, float2 b, float2 c) {
    float2 d;
    asm("fma.rn.f32x2 %0, %1, %2, %3;"
        : "=l"(*(unsigned long long*)&d)
        : "l"(*(unsigned long long*)&a),
          "l"(*(unsigned long long*)&b),
          "l"(*(unsigned long long*)&c));
    return d;
}
__device__ __forceinline__ float2 fmul2(float2 a, float2 b) {
    float2 d;
    asm("mul.rn.f32x2 %0, %1, %2;"
        : "=l"(*(unsigned long long*)&d)
        : "l"(*(unsigned long long*)&a),
          "l"(*(unsigned long long*)&b));
    return d;
}

// ---- cp.async ----
__device__ __forceinline__ void cp_async8(uint32_t dst, const float* src) {
    asm volatile("cp.async.ca.shared.global [%0], [%1], 8;"
                 :: "r"(dst), "l"(src));
}
__device__ __forceinline__ void cp_commit() {
    asm volatile("cp.async.commit_group;");
}
__device__ __forceinline__ void cp_wait0() {
    asm volatile("cp.async.wait_group 0;" ::: "memory");
}

__device__ __forceinline__ void ld8(float* d, const float* p) {
    float4 a = *(const float4*)(p);
    float4 b = *(const float4*)(p + 4);
    d[0] = a.x; d[1] = a.y; d[2] = a.z; d[3] = a.w;
    d[4] = b.x; d[5] = b.y; d[6] = b.z; d[7] = b.w;
}

__device__ __forceinline__ void conv_row(float v[4], const float* r0,
                                         const float* r1, const float* r2,
                                         const float k[9]) {
#pragma unroll
    for (int q = 0; q < 4; ++q) {
        v[q] = r0[q] * k[0] + r0[q + 1] * k[1] + r0[q + 2] * k[2]
             + r1[q] * k[3] + r1[q + 1] * k[4] + r1[q + 2] * k[5]
             + r2[q] * k[6] + r2[q + 1] * k[7] + r2[q + 2] * k[8];
    }
}

// ---- 8-float row: natural pairs only (crossings recomputed per use) ----
struct Row2 {
    float2 p0, p1, p2, p3;  // cols (0,1)(2,3)(4,5)(6,7)
};

__device__ __forceinline__ void ld_row2(Row2& r, const float* sp) {
    float4 A = *(const float4*)sp;
    float4 B = *(const float4*)(sp + 4);
    r.p0 = make_float2(A.x, A.y);
    r.p1 = make_float2(A.z, A.w);
    r.p2 = make_float2(B.x, B.y);
    r.p3 = make_float2(B.z, B.w);
}

// layer-1, 6 outputs as 3 float2; crossing pairs packed inline.
__device__ __forceinline__ void l1row6_v2(float2 o[3], const Row2& r0,
                                          const Row2& r1, const Row2& r2,
                                          const float2 k[9]) {
    float2 a0 = pack2(r0.p0.y, r0.p1.x);
    float2 a1 = pack2(r0.p1.y, r0.p2.x);
    float2 a2 = pack2(r0.p2.y, r0.p3.x);
    float2 b0 = pack2(r1.p0.y, r1.p1.x);
    float2 b1 = pack2(r1.p1.y, r1.p2.x);
    float2 b2 = pack2(r1.p2.y, r1.p3.x);
    float2 c0 = pack2(r2.p0.y, r2.p1.x);
    float2 c1 = pack2(r2.p1.y, r2.p2.x);
    float2 c2 = pack2(r2.p2.y, r2.p3.x);

    o[0] = fmul2(r0.p0, k[0]);
    o[0] = ffma2(a0,    k[1], o[0]);
    o[0] = ffma2(r0.p1, k[2], o[0]);
    o[0] = ffma2(r1.p0, k[3], o[0]);
    o[0] = ffma2(b0,    k[4], o[0]);
    o[0] = ffma2(r1.p1, k[5], o[0]);
    o[0] = ffma2(r2.p0, k[6], o[0]);
    o[0] = ffma2(c0,    k[7], o[0]);
    o[0] = ffma2(r2.p1, k[8], o[0]);

    o[1] = fmul2(r0.p1, k[0]);
    o[1] = ffma2(a1,    k[1], o[1]);
    o[1] = ffma2(r0.p2, k[2], o[1]);
    o[1] = ffma2(r1.p1, k[3], o[1]);
    o[1] = ffma2(b1,    k[4], o[1]);
    o[1] = ffma2(r1.p2, k[5], o[1]);
    o[1] = ffma2(r2.p1, k[6], o[1]);
    o[1] = ffma2(c1,    k[7], o[1]);
    o[1] = ffma2(r2.p2, k[8], o[1]);

    o[2] = fmul2(r0.p2, k[0]);
    o[2] = ffma2(a2,    k[1], o[2]);
    o[2] = ffma2(r0.p3, k[2], o[2]);
    o[2] = ffma2(r1.p2, k[3], o[2]);
    o[2] = ffma2(b2,    k[4], o[2]);
    o[2] = ffma2(r1.p3, k[5], o[2]);
    o[2] = ffma2(r2.p2, k[6], o[2]);
    o[2] = ffma2(c2,    k[7], o[2]);
    o[2] = ffma2(r2.p3, k[8], o[2]);
}

// Fused 2-conv + pool on one interior tile (f32x2 layer-1, scalar layer-2).
__device__ __forceinline__ void fused_tile2(const float* __restrict__ cur,
                                            float* __restrict__ out, int outW,
                                            const float2 k1[9], const float k2[9],
                                            int s, int g, int oy, int ox) {
    const float* sp = cur + (4 * g) * BD + 4 * s;
    Row2 r0, r1, r2;
    float2 a[3], b[3], c[3];
    const float* af = (const float*)a;
    const float* bf = (const float*)b;
    const float* cf = (const float*)c;
    float v[4];

    ld_row2(r0, sp);
    ld_row2(r1, sp + BD);
    ld_row2(r2, sp + 2 * BD);
    l1row6_v2(a, r0, r1, r2, k1);
    ld_row2(r0, sp + 3 * BD);
    l1row6_v2(b, r1, r2, r0, k1);
    ld_row2(r1, sp + 4 * BD);
    l1row6_v2(c, r2, r0, r1, k1);
    conv_row(v, af, bf, cf, k2);
    float m0 = fmaxf(v[0], v[1]);
    float m1 = fmaxf(v[2], v[3]);
    ld_row2(r2, sp + 5 * BD);
    l1row6_v2(a, r0, r1, r2, k1);
    conv_row(v, bf, cf, af, k2);
    {
        float* op = out + (long)(oy + 2 * g) * outW + ox + 2 * s;
        *(float2*)op = make_float2(fmaxf(m0, fmaxf(v[0], v[1])),
                                   fmaxf(m1, fmaxf(v[2], v[3])));
    }
    ld_row2(r0, sp + 6 * BD);
    l1row6_v2(b, r1, r2, r0, k1);
    conv_row(v, cf, af, bf, k2);
    m0 = fmaxf(v[0], v[1]);
    m1 = fmaxf(v[2], v[3]);
    ld_row2(r1, sp + 7 * BD);
    l1row6_v2(c, r2, r0, r1, k1);
    conv_row(v, af, bf, cf, k2);
    {
        float* op = out + (long)(oy + 2 * g + 1) * outW + ox + 2 * s;
        *(float2*)op = make_float2(fmaxf(m0, fmaxf(v[0], v[1])),
                                   fmaxf(m1, fmaxf(v[2], v[3])));
    }
}

// ============ persistent pipelined K=2 kernel (interior tiles) ============
// WT compile-time -> cheap tile index math; 3 CTAs/SM target.
template <int WT>
__global__ __launch_bounds__(NTP, 3)
void stage2p_kernel(const float* __restrict__ in, int inW,
                    float* __restrict__ out, int outW,
                    const float* __restrict__ w0,
                    const float* __restrict__ w1) {
    constexpr int IT  = WT - 2;
    constexpr int NTI = IT * IT;
    __shared__ float bufA[BD * BD];
    __shared__ float bufB[BD * BD];
    __shared__ float wts[18];

    const int tid = threadIdx.x;
    if (tid < 18) wts[tid] = (tid < 9) ? w0[tid] : w1[tid - 9];

    int q = blockIdx.x;
    if (q >= NTI) return;

    const int tc = tid % 36;  // float2 column
    const int tr = tid / 36;  // row 0..7
    const int NC = gridDim.x;

    int ty = q / IT + 1, tx = q % IT + 1;

    const uint32_t sA = (uint32_t)__cvta_generic_to_shared(bufA);
    const uint32_t sB = (uint32_t)__cvta_generic_to_shared(bufB);

    // prologue: stage tile q into bufA
    {
        const float* gp = in + ((long)ty * 64 - 2 + tr) * inW
                             + (long)tx * 64 - 2 + 2 * tc;
        uint32_t dp = sA + (tr * BD + 2 * tc) * 4;
#pragma unroll
        for (int r = 0; r < 9; ++r)
            cp_async8(dp + r * 8 * BD * 4, gp + (long)8 * r * inW);
        cp_commit();
    }
    cp_wait0();
    __syncthreads();

    float2 k1[9];
    float  k2[9];
#pragma unroll
    for (int m = 0; m < 9; ++m) {
        float kv = wts[m];
        k1[m] = pack2(kv, kv);
        k2[m] = wts[9 + m];
    }

    const float* cur = bufA;
    uint32_t     nxt = sB;
    const int s = tid & 15;
    const int g = (tid < 256) ? (tid >> 4) : 0;

    while (true) {
        const int  qn = q + NC;
        const bool hasnext = qn < NTI;

        if (hasnext) {
            int tyn = qn / IT + 1, txn = qn % IT + 1;
            const float* gp = in + ((long)tyn * 64 - 2 + tr) * inW
                                 + (long)txn * 64 - 2 + 2 * tc;
            uint32_t dp = nxt + (tr * BD + 2 * tc) * 4;
#pragma unroll
            for (int r = 0; r < 9; ++r)
                cp_async8(dp + r * 8 * BD * 4, gp + (long)8 * r * inW);
            cp_commit();
        }

        if (tid < 256)
            fused_tile2(cur, out, outW, k1, k2, s, g, ty * 32, tx * 32);

        if (!hasnext) break;

        cp_wait0();
        __syncthreads();

        q = qn; ty = q / IT + 1; tx = q % IT + 1;
        const float* t = cur;
        cur = (cur == bufA) ? bufB : bufA;
        nxt = (t == bufA) ? sA : sB;
    }
}

// ============ edge-ring K=2 kernel (unchanged) ============
template <bool EDGE>
__device__ __forceinline__ void layer_mid2(const float* __restrict__ src,
                                           float* __restrict__ dst,
                                           const float k[9], int s, int g,
                                           int ey0, int ex0, unsigned uw) {
    const float* sp = src + (4 * g) * BD + 4 * s;
    float r[3][8];
    ld8(r[0], sp);
    ld8(r[1], sp + BD);
#pragma unroll
    for (int j = 0; j < 4; ++j) {
        ld8(r[(j + 2) % 3], sp + (2 + j) * BD);
        float v[4];
        conv_row(v, r[j % 3], r[(j + 1) % 3], r[(j + 2) % 3], k);
        if (EDGE) {
            const bool rok = (unsigned)(ey0 + 4 * g + j) < uw;
#pragma unroll
            for (int q = 0; q < 4; ++q)
                if (!(rok && ((unsigned)(ex0 + 4 * s + q) < uw))) v[q] = 0.0f;
        }
        *(float4*)(dst + (4 * g + j) * BD + 4 * s) =
            make_float4(v[0], v[1], v[2], v[3]);
    }
}

__global__ __launch_bounds__(NT, 3)
void stage2e_kernel(const float* __restrict__ in, int inW,
                    float* __restrict__ out, int outW,
                    const float* __restrict__ w0,
                    const float* __restrict__ w1, int WT) {
    constexpr int EXT = 68;
    __shared__ float bufA[BD * BD];
    __shared__ float bufB[BD * BD];
    __shared__ float wts[18];

    const int tid = threadIdx.x;
    if (tid < 18) wts[tid] = (tid < 9) ? w0[tid] : w1[tid - 9];

    const int b = blockIdx.x;
    int tx, ty;
    if (b < WT)              { tx = b;        ty = 0; }
    else if (b < 2 * WT)     { tx = b - WT;   ty = WT - 1; }
    else if (b < 3 * WT - 2) { tx = 0;        ty = b - 2 * WT + 1; }
    else                     { tx = WT - 1;   ty = b - (3 * WT - 2) + 1; }

    const int gx0 = tx * 64 - 2;
    const int gy0 = ty * 64 - 2;
    const unsigned uw = (unsigned)inW;
    const int ox = tx * 32, oy = ty * 32;

    for (int i = tid; i < BD * BD; i += NT) {
        int r = i / BD, c = i - r * BD;
        float v = 0.0f;
        if (r < EXT && c < EXT) {
            int gy = gy0 + r, gx = gx0 + c;
            if ((unsigned)gy < uw && (unsigned)gx < uw)
                v = in[(long)gy * inW + gx];
        }
        bufA[i] = v;
        bufB[i] = 0.0f;
    }
    __syncthreads();

    const bool active = tid < 289;
    const int s = tid % 17;
    const int g = tid / 17;
    float k[9];

    if (active) {
#pragma unroll
        for (int m = 0; m < 9; ++m) k[m] = wts[m];
        layer_mid2<true>(bufA, bufB, k, s, g, gy0 + 1, gx0 + 1, uw);
    }
    __syncthreads();
    if (active) {
#pragma unroll
        for (int m = 0; m < 9; ++m) k[m] = wts[9 + m];
        layer_mid2<true>(bufB, bufA, k, s, g, gy0 + 2, gx0 + 2, uw);
    }
    __syncthreads();
    for (int i = tid; i < 1024; i += NT) {
        int py = i >> 5, px = i & 31;
        const float* p = bufA + (2 * py) * BD + 2 * px;
        float m = fmaxf(fmaxf(p[0], p[1]), fmaxf(p[BD], p[BD + 1]));
        out[(long)(oy + py) * outW + ox + px] = m;
    }
}

// ============ K=3 stage kernel (C, D) — unchanged ============
template <int BDT>
__device__ __forceinline__ void layer_last_pool3(const float* __restrict__ src,
                                                 float* __restrict__ out,
                                                 int outW, const float k[9],
                                                 int s, int g, int oy, int ox) {
    const float* sp = src + (4 * g) * BDT + 4 * s;
    float r[3][8];
    ld8(r[0], sp);
    ld8(r[1], sp + BDT);
    float p[2][2];
#pragma unroll
    for (int j = 0; j < 4; ++j) {
        ld8(r[(j + 2) % 3], sp + (2 + j) * BDT);
        float v[4];
        conv_row(v, r[j % 3], r[(j + 1) % 3], r[(j + 2) % 3], k);
        const int pr = j >> 1;
        float m0 = fmaxf(v[0], v[1]);
        float m1 = fmaxf(v[2], v[3]);
        if ((j & 1) == 0) { p[pr][0] = m0; p[pr][1] = m1; }
        else             { p[pr][0] = fmaxf(p[pr][0], m0);
                           p[pr][1] = fmaxf(p[pr][1], m1); }
    }
    float* op = out + (long)(oy + 2 * g) * outW + (ox + 2 * s);
    *(float2*)op = make_float2(p[0][0], p[0][1]);
    *(float2*)(op + outW) = make_float2(p[1][0], p[1][1]);
}

template <int BDT, bool EDGE>
__device__ __forceinline__ void layer_mid3(const float* __restrict__ src,
                                           float* __restrict__ dst,
                                           const float k[9], int s, int g,
                                           int ey0, int ex0, unsigned uw) {
    const float* sp = src + (4 * g) * BDT + 4 * s;
    float r[3][8];
    ld8(r[0], sp);
    ld8(r[1], sp + BDT);
#pragma unroll
    for (int j = 0; j < 4; ++j) {
        ld8(r[(j + 2) % 3], sp + (2 + j) * BDT);
        float v[4];
        conv_row(v, r[j % 3], r[(j + 1) % 3], r[(j + 2) % 3], k);
        if (EDGE) {
            const bool rok = (unsigned)(ey0 + 4 * g + j) < uw;
#pragma unroll
            for (int q = 0; q < 4; ++q)
                if (!(rok && ((unsigned)(ex0 + 4 * s + q) < uw))) v[q] = 0.0f;
        }
        *(float4*)(dst + (4 * g + j) * BDT + 4 * s) =
            make_float4(v[0], v[1], v[2], v[3]);
    }
}

template <int K, int TO, int NTT, int MINCTA>
__global__ __launch_bounds__(NTT, MINCTA)
void stage_kernel(const float* __restrict__ in, int inW,
                  float* __restrict__ out, int outW,
                  const float* __restrict__ w0,
                  const float* __restrict__ w1,
                  const float* __restrict__ w2) {
    constexpr int EXT    = 2 * TO + 2 * K;
    constexpr int STRIPS = (2 * TO + 2 * (K - 1) + 3) / 4;
    constexpr int NACT   = STRIPS * STRIPS;
    constexpr int BDv    = (EXT > 4 * STRIPS + 4) ? EXT : (4 * STRIPS + 4);
    constexpr int BDT    = (BDv + 3) & ~3;

    __shared__ float bufA[BDT * BDT];
    __shared__ float bufB[BDT * BDT];
    __shared__ float wts[27];

    const int tid = threadIdx.x;
    if (tid < K * 9) {
        const float* wp = (tid < 9) ? w0 : ((tid < 18) ? w1 : w2);
        wts[tid] = wp[tid % 9];
    }

    const int gx0 = blockIdx.x * 2 * TO - K;
    const int gy0 = blockIdx.y * 2 * TO - K;
    const unsigned uw = (unsigned)inW;
    const bool edge = (gx0 < 0) || (gy0 < 0) ||
                      (gx0 + EXT > inW) || (gy0 + EXT > inW);

    if (!edge) {
        for (int i = tid; i < BDT * BDT; i += NTT) {
            int r = i / BDT, c = i - r * BDT;
            if (r < EXT && c < EXT)
                bufA[i] = in[(long)(gy0 + r) * inW + (gx0 + c)];
        }
    } else {
        for (int i = tid; i < BDT * BDT; i += NTT) {
            int r = i / BDT, c = i - r * BDT;
            float v = 0.0f;
            if (r < EXT && c < EXT) {
                int gy = gy0 + r, gx = gx0 + c;
                if ((unsigned)gy < uw && (unsigned)gx < uw)
                    v = in[(long)gy * inW + gx];
            }
            bufA[i] = v;
            bufB[i] = 0.0f;
        }
    }
    __syncthreads();

    const bool active = tid < NACT;
    const int s = tid % STRIPS;
    const int g = tid / STRIPS;
    const int ox = blockIdx.x * TO, oy = blockIdx.y * TO;

    float k[9];
    float* src = bufA;
    float* dst = bufB;

#pragma unroll
    for (int c = 0; c < K - 1; ++c) {
        if (active) {
#pragma unroll
            for (int m = 0; m < 9; ++m) k[m] = wts[c * 9 + m];
            if (edge) layer_mid3<BDT, true >(src, dst, k, s, g,
                                             gy0 + c + 1, gx0 + c + 1, uw);
            else      layer_mid3<BDT, false>(src, dst, k, s, g, 0, 0, uw);
        }
        __syncthreads();
        float* t = src; src = dst; dst = t;
    }

    if (!edge) {
        if (active && s < TO / 2 && g < TO / 2) {
#pragma unroll
            for (int m = 0; m < 9; ++m) k[m] = wts[(K - 1) * 9 + m];
            layer_last_pool3<BDT>(src, out, outW, k, s, g, oy, ox);
        }
    } else {
        if (active) {
#pragma unroll
            for (int m = 0; m < 9; ++m) k[m] = wts[(K - 1) * 9 + m];
            layer_mid3<BDT, true>(src, dst, k, s, g, gy0 + K, gx0 + K, uw);
        }
        __syncthreads();
        for (int i = tid; i < TO * TO; i += NTT) {
            int py = i / TO, px = i % TO;
            const float* p = dst + (2 * py) * BDT + 2 * px;
            float m = fmaxf(fmaxf(p[0], p[1]), fmaxf(p[BDT], p[BDT + 1]));
            out[(long)(oy + py) * outW + ox + px] = m;
        }
    }
}

extern "C" void kernel_launch(void* const* d_in, const int* in_sizes, int n_in,
                              void* d_out, int out_size) {
    const float* x = (const float*)d_in[0];
    const float* w[10];
    for (int i = 0; i < 10; ++i) w[i] = (const float*)d_in[1 + i];

    float *b0, *b1, *b2;
    cudaGetSymbolAddress((void**)&b0, g_buf0);
    cudaGetSymbolAddress((void**)&b1, g_buf1);
    cudaGetSymbolAddress((void**)&b2, g_buf2);

    float* outp = (float*)d_out;

    stage2e_kernel<<<4 * 128 - 4, NT>>>(x, 8192, b0, 4096, w[0], w[1], 128);
    stage2p_kernel<128><<<444, NTP>>>(x, 8192, b0, 4096, w[0], w[1]);
    stage2e_kernel<<<4 * 64 - 4,  NT>>>(b0, 4096, b1, 2048, w[2], w[3], 64);
    stage2p_kernel<64><<<444, NTP>>>(b0, 4096, b1, 2048, w[2], w[3]);
    stage_kernel<3, 32, 320, 4><<<dim3(32, 32), 320>>>(b1, 2048, b2, 1024, w[4], w[5], w[6]);
    stage_kernel<3, 16, 128, 8><<<dim3(32, 32), 128>>>(b2, 1024, outp, 512, w[7], w[8], w[9]);
}

// round 17
// speedup vs baseline: 1.3785x; 1.1851x over previous
#include <cuda_runtime.h>
#include <cstdint>

// 8192x8192 fp32 input; 10 3x3 SAME convs; 4 2x2 maxpools.
// R17 = R16 with edge tiles folded INTO the persistent kernels (no separate
//       edge launches, no inter-kernel serialization bubble). C,D unchanged.

__device__ float g_buf0[4096u * 4096u];
__device__ float g_buf1[2048u * 2048u];
__device__ float g_buf2[1024u * 1024u];

#define NT  320   // K=3 kernels
#define NTP 288   // persistent kernel
#define BD  72

// ---- f32x2 primitives ----
__device__ __forceinline__ float2 pack2(float x, float y) {
    float2 r;
    asm("mov.b64 %0, {%1, %2};"
        : "=l"(*(unsigned long long*)&r) : "f"(x), "f"(y));
    return r;
}
__device__ __forceinline__ float2 ffma2(float2 a, float2 b, float2 c) {
    float2 d;
    asm("fma.rn.f32x2 %0, %1, %2, %3;"
        : "=l"(*(unsigned long long*)&d)
        : "l"(*(unsigned long long*)&a),
          "l"(*(unsigned long long*)&b),
          "l"(*(unsigned long long*)&c));
    return d;
}
__device__ __forceinline__ float2 fmul2(float2 a, float2 b) {
    float2 d;
    asm("mul.rn.f32x2 %0, %1, %2;"
        : "=l"(*(unsigned long long*)&d)
        : "l"(*(unsigned long long*)&a),
          "l"(*(unsigned long long*)&b));
    return d;
}

// ---- cp.async ----
__device__ __forceinline__ void cp_async8(uint32_t dst, const float* src) {
    asm volatile("cp.async.ca.shared.global [%0], [%1], 8;"
                 :: "r"(dst), "l"(src));
}
__device__ __forceinline__ void cp_commit() {
    asm volatile("cp.async.commit_group;");
}
__device__ __forceinline__ void cp_wait0() {
    asm volatile("cp.async.wait_group 0;" ::: "memory");
}

__device__ __forceinline__ void ld8(float* d, const float* p) {
    float4 a = *(const float4*)(p);
    float4 b = *(const float4*)(p + 4);
    d[0] = a.x; d[1] = a.y; d[2] = a.z; d[3] = a.w;
    d[4] = b.x; d[5] = b.y; d[6] = b.z; d[7] = b.w;
}

__device__ __forceinline__ void conv_row(float v[4], const float* r0,
                                         const float* r1, const float* r2,
                                         const float k[9]) {
#pragma unroll
    for (int q = 0; q < 4; ++q) {
        v[q] = r0[q] * k[0] + r0[q + 1] * k[1] + r0[q + 2] * k[2]
             + r1[q] * k[3] + r1[q + 1] * k[4] + r1[q + 2] * k[5]
             + r2[q] * k[6] + r2[q + 1] * k[7] + r2[q + 2] * k[8];
    }
}

// ---- 8-float row as natural f32x2 pairs ----
struct Row2 {
    float2 p0, p1, p2, p3;  // cols (0,1)(2,3)(4,5)(6,7)
};

__device__ __forceinline__ void ld_row2(Row2& r, const float* sp) {
    float4 A = *(const float4*)sp;
    float4 B = *(const float4*)(sp + 4);
    r.p0 = make_float2(A.x, A.y);
    r.p1 = make_float2(A.z, A.w);
    r.p2 = make_float2(B.x, B.y);
    r.p3 = make_float2(B.z, B.w);
}

// layer-1, 6 outputs as 3 float2; crossing pairs packed inline.
__device__ __forceinline__ void l1row6_v2(float2 o[3], const Row2& r0,
                                          const Row2& r1, const Row2& r2,
                                          const float2 k[9]) {
    float2 a0 = pack2(r0.p0.y, r0.p1.x);
    float2 a1 = pack2(r0.p1.y, r0.p2.x);
    float2 a2 = pack2(r0.p2.y, r0.p3.x);
    float2 b0 = pack2(r1.p0.y, r1.p1.x);
    float2 b1 = pack2(r1.p1.y, r1.p2.x);
    float2 b2 = pack2(r1.p2.y, r1.p3.x);
    float2 c0 = pack2(r2.p0.y, r2.p1.x);
    float2 c1 = pack2(r2.p1.y, r2.p2.x);
    float2 c2 = pack2(r2.p2.y, r2.p3.x);

    o[0] = fmul2(r0.p0, k[0]);
    o[0] = ffma2(a0,    k[1], o[0]);
    o[0] = ffma2(r0.p1, k[2], o[0]);
    o[0] = ffma2(r1.p0, k[3], o[0]);
    o[0] = ffma2(b0,    k[4], o[0]);
    o[0] = ffma2(r1.p1, k[5], o[0]);
    o[0] = ffma2(r2.p0, k[6], o[0]);
    o[0] = ffma2(c0,    k[7], o[0]);
    o[0] = ffma2(r2.p1, k[8], o[0]);

    o[1] = fmul2(r0.p1, k[0]);
    o[1] = ffma2(a1,    k[1], o[1]);
    o[1] = ffma2(r0.p2, k[2], o[1]);
    o[1] = ffma2(r1.p1, k[3], o[1]);
    o[1] = ffma2(b1,    k[4], o[1]);
    o[1] = ffma2(r1.p2, k[5], o[1]);
    o[1] = ffma2(r2.p1, k[6], o[1]);
    o[1] = ffma2(c1,    k[7], o[1]);
    o[1] = ffma2(r2.p2, k[8], o[1]);

    o[2] = fmul2(r0.p2, k[0]);
    o[2] = ffma2(a2,    k[1], o[2]);
    o[2] = ffma2(r0.p3, k[2], o[2]);
    o[2] = ffma2(r1.p2, k[3], o[2]);
    o[2] = ffma2(b2,    k[4], o[2]);
    o[2] = ffma2(r1.p3, k[5], o[2]);
    o[2] = ffma2(r2.p2, k[6], o[2]);
    o[2] = ffma2(c2,    k[7], o[2]);
    o[2] = ffma2(r2.p3, k[8], o[2]);
}

// Fused 2-conv + pool on one interior tile (proven R16 body).
__device__ __forceinline__ void fused_tile2(const float* __restrict__ cur,
                                            float* __restrict__ out, int outW,
                                            const float2 k1[9], const float k2[9],
                                            int s, int g, int oy, int ox) {
    const float* sp = cur + (4 * g) * BD + 4 * s;
    Row2 r0, r1, r2;
    float2 a[3], b[3], c[3];
    const float* af = (const float*)a;
    const float* bf = (const float*)b;
    const float* cf = (const float*)c;
    float v[4];

    ld_row2(r0, sp);
    ld_row2(r1, sp + BD);
    ld_row2(r2, sp + 2 * BD);
    l1row6_v2(a, r0, r1, r2, k1);
    ld_row2(r0, sp + 3 * BD);
    l1row6_v2(b, r1, r2, r0, k1);
    ld_row2(r1, sp + 4 * BD);
    l1row6_v2(c, r2, r0, r1, k1);
    conv_row(v, af, bf, cf, k2);
    float m0 = fmaxf(v[0], v[1]);
    float m1 = fmaxf(v[2], v[3]);
    ld_row2(r2, sp + 5 * BD);
    l1row6_v2(a, r0, r1, r2, k1);
    conv_row(v, bf, cf, af, k2);
    {
        float* op = out + (long)(oy + 2 * g) * outW + ox + 2 * s;
        *(float2*)op = make_float2(fmaxf(m0, fmaxf(v[0], v[1])),
                                   fmaxf(m1, fmaxf(v[2], v[3])));
    }
    ld_row2(r0, sp + 6 * BD);
    l1row6_v2(b, r1, r2, r0, k1);
    conv_row(v, cf, af, bf, k2);
    m0 = fmaxf(v[0], v[1]);
    m1 = fmaxf(v[2], v[3]);
    ld_row2(r1, sp + 7 * BD);
    l1row6_v2(c, r2, r0, r1, k1);
    conv_row(v, af, bf, cf, k2);
    {
        float* op = out + (long)(oy + 2 * g + 1) * outW + ox + 2 * s;
        *(float2*)op = make_float2(fmaxf(m0, fmaxf(v[0], v[1])),
                                   fmaxf(m1, fmaxf(v[2], v[3])));
    }
}

// Edge-tile variant: l1 outputs zeroed where their IMAGE coords are outside
// (SAME zero-padding re-applied after layer 1). The pooled l2 outputs are
// always in-image, so l2 needs no mask. Input buffer has OOB cells zeroed
// by the fixup pass.
__device__ __forceinline__ void fused_tile2e(const float* __restrict__ cur,
                                             float* __restrict__ out, int outW,
                                             const float2 k1[9], const float k2[9],
                                             int s, int g, int oy, int ox,
                                             int gy0, int gx0, unsigned uw) {
    const float* sp = cur + (4 * g) * BD + 4 * s;
    float2 cm[3];
#pragma unroll
    for (int j = 0; j < 3; ++j) {
        int c0 = gx0 + 4 * s + 1 + 2 * j;
        cm[j] = make_float2((unsigned)c0 < uw ? 1.f : 0.f,
                            (unsigned)(c0 + 1) < uw ? 1.f : 0.f);
    }
    const int gyb = gy0 + 4 * g;  // buffer row 0 global y

    Row2 r0, r1, r2;
    float2 a[3], b[3], c[3];
    const float* af = (const float*)a;
    const float* bf = (const float*)b;
    const float* cf = (const float*)c;
    float v[4];

#define L1M(dst, q0, q1, q2, t)                                             \
    do {                                                                    \
        l1row6_v2(dst, q0, q1, q2, k1);                                     \
        float rm_ = (unsigned)(gyb + (t)) < uw ? 1.f : 0.f;                 \
        _Pragma("unroll")                                                   \
        for (int j_ = 0; j_ < 3; ++j_)                                      \
            dst[j_] = fmul2(dst[j_],                                        \
                            make_float2(cm[j_].x * rm_, cm[j_].y * rm_));   \
    } while (0)

    ld_row2(r0, sp);
    ld_row2(r1, sp + BD);
    ld_row2(r2, sp + 2 * BD);
    L1M(a, r0, r1, r2, 1);
    ld_row2(r0, sp + 3 * BD);
    L1M(b, r1, r2, r0, 2);
    ld_row2(r1, sp + 4 * BD);
    L1M(c, r2, r0, r1, 3);
    conv_row(v, af, bf, cf, k2);
    float m0 = fmaxf(v[0], v[1]);
    float m1 = fmaxf(v[2], v[3]);
    ld_row2(r2, sp + 5 * BD);
    L1M(a, r0, r1, r2, 4);
    conv_row(v, bf, cf, af, k2);
    {
        float* op = out + (long)(oy + 2 * g) * outW + ox + 2 * s;
        *(float2*)op = make_float2(fmaxf(m0, fmaxf(v[0], v[1])),
                                   fmaxf(m1, fmaxf(v[2], v[3])));
    }
    ld_row2(r0, sp + 6 * BD);
    L1M(b, r1, r2, r0, 5);
    conv_row(v, cf, af, bf, k2);
    m0 = fmaxf(v[0], v[1]);
    m1 = fmaxf(v[2], v[3]);
    ld_row2(r1, sp + 7 * BD);
    L1M(c, r2, r0, r1, 6);
    conv_row(v, af, bf, cf, k2);
    {
        float* op = out + (long)(oy + 2 * g + 1) * outW + ox + 2 * s;
        *(float2*)op = make_float2(fmaxf(m0, fmaxf(v[0], v[1])),
                                   fmaxf(m1, fmaxf(v[2], v[3])));
    }
#undef L1M
}

// Stage one tile via cp.async; edge tiles use clamped (in-bounds) sources.
template <int WT>
__device__ __forceinline__ void stage_tile(const float* __restrict__ in,
                                           int inW, int q, uint32_t dst,
                                           int tc, int tr) {
    const int ty = q / WT, tx = q % WT;
    const bool edge = (tx == 0) | (ty == 0) | (tx == WT - 1) | (ty == WT - 1);
    const long gy = (long)ty * 64 - 2 + tr;
    const long gx = (long)tx * 64 - 2 + 2 * tc;
    uint32_t dp = dst + (tr * BD + 2 * tc) * 4;
    if (!edge) {
        const float* gp = in + gy * inW + gx;
#pragma unroll
        for (int r = 0; r < 9; ++r)
            cp_async8(dp + r * 8 * BD * 4, gp + (long)8 * r * inW);
    } else {
        long gxc = gx < 0 ? 0 : (gx > inW - 2 ? inW - 2 : gx);  // stays even
#pragma unroll
        for (int r = 0; r < 9; ++r) {
            long gyr = gy + 8 * r;
            long gyc = gyr < 0 ? 0 : (gyr > inW - 1 ? inW - 1 : gyr);
            cp_async8(dp + r * 8 * BD * 4, in + gyc * inW + gxc);
        }
    }
    cp_commit();
}

// Zero smem cells whose image coords are outside (edge tiles only).
template <int WT>
__device__ __forceinline__ void fixup_tile(float* buf, int q, unsigned uw,
                                           int tid) {
    const int ty = q / WT, tx = q % WT;
    const int gy0 = ty * 64 - 2, gx0 = tx * 64 - 2;
    for (int i = tid; i < BD * BD; i += NTP) {
        int r = i / BD, c = i - r * BD;
        if ((unsigned)(gy0 + r) >= uw || (unsigned)(gx0 + c) >= uw)
            buf[i] = 0.0f;
    }
}

// ============ persistent pipelined K=2 kernel (ALL tiles) ============
template <int WT>
__global__ __launch_bounds__(NTP, 3)
void stage2p_kernel(const float* __restrict__ in, int inW,
                    float* __restrict__ out, int outW,
                    const float* __restrict__ w0,
                    const float* __restrict__ w1) {
    constexpr int NTI = WT * WT;
    __shared__ float bufA[BD * BD];
    __shared__ float bufB[BD * BD];
    __shared__ float wts[18];

    const int tid = threadIdx.x;
    if (tid < 18) wts[tid] = (tid < 9) ? w0[tid] : w1[tid - 9];

    int q = blockIdx.x;
    if (q >= NTI) return;

    const int tc = tid % 36;
    const int tr = tid / 36;
    const int NC = gridDim.x;
    const unsigned uw = (unsigned)inW;

    float*   curp = bufA;
    float*   nxtp = bufB;
    uint32_t curs = (uint32_t)__cvta_generic_to_shared(bufA);
    uint32_t nxts = (uint32_t)__cvta_generic_to_shared(bufB);

    // prologue
    stage_tile<WT>(in, inW, q, curs, tc, tr);
    cp_wait0();
    __syncthreads();
    {
        int ty = q / WT, tx = q % WT;
        if ((tx == 0) | (ty == 0) | (tx == WT - 1) | (ty == WT - 1)) {
            fixup_tile<WT>(curp, q, uw, tid);
            __syncthreads();
        }
    }

    float2 k1[9];
    float  k2[9];
#pragma unroll
    for (int m = 0; m < 9; ++m) {
        float kv = wts[m];
        k1[m] = pack2(kv, kv);
        k2[m] = wts[9 + m];
    }

    const int s = tid & 15;
    const int g = (tid < 256) ? (tid >> 4) : 0;

    while (true) {
        const int  qn = q + NC;
        const bool hasnext = qn < NTI;

        if (hasnext) stage_tile<WT>(in, inW, qn, nxts, tc, tr);

        {
            const int ty = q / WT, tx = q % WT;
            const bool ce = (tx == 0) | (ty == 0) | (tx == WT - 1) | (ty == WT - 1);
            if (tid < 256) {
                if (ce)
                    fused_tile2e(curp, out, outW, k1, k2, s, g,
                                 ty * 32, tx * 32, ty * 64 - 2, tx * 64 - 2, uw);
                else
                    fused_tile2(curp, out, outW, k1, k2, s, g, ty * 32, tx * 32);
            }
        }

        if (!hasnext) break;

        cp_wait0();
        __syncthreads();
        {
            int ty = qn / WT, tx = qn % WT;
            if ((tx == 0) | (ty == 0) | (tx == WT - 1) | (ty == WT - 1)) {
                fixup_tile<WT>(nxtp, qn, uw, tid);
                __syncthreads();
            }
        }

        q = qn;
        float* tp = curp; curp = nxtp; nxtp = tp;
        uint32_t ts = curs; curs = nxts; nxts = ts;
    }
}

// ============ K=3 stage kernel (C, D) — unchanged ============
template <int BDT>
__device__ __forceinline__ void layer_last_pool3(const float* __restrict__ src,
                                                 float* __restrict__ out,
                                                 int outW, const float k[9],
                                                 int s, int g, int oy, int ox) {
    const float* sp = src + (4 * g) * BDT + 4 * s;
    float r[3][8];
    ld8(r[0], sp);
    ld8(r[1], sp + BDT);
    float p[2][2];
#pragma unroll
    for (int j = 0; j < 4; ++j) {
        ld8(r[(j + 2) % 3], sp + (2 + j) * BDT);
        float v[4];
        conv_row(v, r[j % 3], r[(j + 1) % 3], r[(j + 2) % 3], k);
        const int pr = j >> 1;
        float m0 = fmaxf(v[0], v[1]);
        float m1 = fmaxf(v[2], v[3]);
        if ((j & 1) == 0) { p[pr][0] = m0; p[pr][1] = m1; }
        else             { p[pr][0] = fmaxf(p[pr][0], m0);
                           p[pr][1] = fmaxf(p[pr][1], m1); }
    }
    float* op = out + (long)(oy + 2 * g) * outW + (ox + 2 * s);
    *(float2*)op = make_float2(p[0][0], p[0][1]);
    *(float2*)(op + outW) = make_float2(p[1][0], p[1][1]);
}

template <int BDT, bool EDGE>
__device__ __forceinline__ void layer_mid3(const float* __restrict__ src,
                                           float* __restrict__ dst,
                                           const float k[9], int s, int g,
                                           int ey0, int ex0, unsigned uw) {
    const float* sp = src + (4 * g) * BDT + 4 * s;
    float r[3][8];
    ld8(r[0], sp);
    ld8(r[1], sp + BDT);
#pragma unroll
    for (int j = 0; j < 4; ++j) {
        ld8(r[(j + 2) % 3], sp + (2 + j) * BDT);
        float v[4];
        conv_row(v, r[j % 3], r[(j + 1) % 3], r[(j + 2) % 3], k);
        if (EDGE) {
            const bool rok = (unsigned)(ey0 + 4 * g + j) < uw;
#pragma unroll
            for (int q = 0; q < 4; ++q)
                if (!(rok && ((unsigned)(ex0 + 4 * s + q) < uw))) v[q] = 0.0f;
        }
        *(float4*)(dst + (4 * g + j) * BDT + 4 * s) =
            make_float4(v[0], v[1], v[2], v[3]);
    }
}

template <int K, int TO, int NTT, int MINCTA>
__global__ __launch_bounds__(NTT, MINCTA)
void stage_kernel(const float* __restrict__ in, int inW,
                  float* __restrict__ out, int outW,
                  const float* __restrict__ w0,
                  const float* __restrict__ w1,
                  const float* __restrict__ w2) {
    constexpr int EXT    = 2 * TO + 2 * K;
    constexpr int STRIPS = (2 * TO + 2 * (K - 1) + 3) / 4;
    constexpr int NACT   = STRIPS * STRIPS;
    constexpr int BDv    = (EXT > 4 * STRIPS + 4) ? EXT : (4 * STRIPS + 4);
    constexpr int BDT    = (BDv + 3) & ~3;

    __shared__ float bufA[BDT * BDT];
    __shared__ float bufB[BDT * BDT];
    __shared__ float wts[27];

    const int tid = threadIdx.x;
    if (tid < K * 9) {
        const float* wp = (tid < 9) ? w0 : ((tid < 18) ? w1 : w2);
        wts[tid] = wp[tid % 9];
    }

    const int gx0 = blockIdx.x * 2 * TO - K;
    const int gy0 = blockIdx.y * 2 * TO - K;
    const unsigned uw = (unsigned)inW;
    const bool edge = (gx0 < 0) || (gy0 < 0) ||
                      (gx0 + EXT > inW) || (gy0 + EXT > inW);

    if (!edge) {
        for (int i = tid; i < BDT * BDT; i += NTT) {
            int r = i / BDT, c = i - r * BDT;
            if (r < EXT && c < EXT)
                bufA[i] = in[(long)(gy0 + r) * inW + (gx0 + c)];
        }
    } else {
        for (int i = tid; i < BDT * BDT; i += NTT) {
            int r = i / BDT, c = i - r * BDT;
            float v = 0.0f;
            if (r < EXT && c < EXT) {
                int gy = gy0 + r, gx = gx0 + c;
                if ((unsigned)gy < uw && (unsigned)gx < uw)
                    v = in[(long)gy * inW + gx];
            }
            bufA[i] = v;
            bufB[i] = 0.0f;
        }
    }
    __syncthreads();

    const bool active = tid < NACT;
    const int s = tid % STRIPS;
    const int g = tid / STRIPS;
    const int ox = blockIdx.x * TO, oy = blockIdx.y * TO;

    float k[9];
    float* src = bufA;
    float* dst = bufB;

#pragma unroll
    for (int c = 0; c < K - 1; ++c) {
        if (active) {
#pragma unroll
            for (int m = 0; m < 9; ++m) k[m] = wts[c * 9 + m];
            if (edge) layer_mid3<BDT, true >(src, dst, k, s, g,
                                             gy0 + c + 1, gx0 + c + 1, uw);
            else      layer_mid3<BDT, false>(src, dst, k, s, g, 0, 0, uw);
        }
        __syncthreads();
        float* t = src; src = dst; dst = t;
    }

    if (!edge) {
        if (active && s < TO / 2 && g < TO / 2) {
#pragma unroll
            for (int m = 0; m < 9; ++m) k[m] = wts[(K - 1) * 9 + m];
            layer_last_pool3<BDT>(src, out, outW, k, s, g, oy, ox);
        }
    } else {
        if (active) {
#pragma unroll
            for (int m = 0; m < 9; ++m) k[m] = wts[(K - 1) * 9 + m];
            layer_mid3<BDT, true>(src, dst, k, s, g, gy0 + K, gx0 + K, uw);
        }
        __syncthreads();
        for (int i = tid; i < TO * TO; i += NTT) {
            int py = i / TO, px = i % TO;
            const float* p = dst + (2 * py) * BDT + 2 * px;
            float m = fmaxf(fmaxf(p[0], p[1]), fmaxf(p[BDT], p[BDT + 1]));
            out[(long)(oy + py) * outW + ox + px] = m;
        }
    }
}

extern "C" void kernel_launch(void* const* d_in, const int* in_sizes, int n_in,
                              void* d_out, int out_size) {
    const float* x = (const float*)d_in[0];
    const float* w[10];
    for (int i = 0; i < 10; ++i) w[i] = (const float*)d_in[1 + i];

    float *b0, *b1, *b2;
    cudaGetSymbolAddress((void**)&b0, g_buf0);
    cudaGetSymbolAddress((void**)&b1, g_buf1);
    cudaGetSymbolAddress((void**)&b2, g_buf2);

    float* outp = (float*)d_out;

    stage2p_kernel<128><<<444, NTP>>>(x,  8192, b0, 4096, w[0], w[1]);
    stage2p_kernel<64> <<<444, NTP>>>(b0, 4096, b1, 2048, w[2], w[3]);
    stage_kernel<3, 32, 320, 4><<<dim3(32, 32), 320>>>(b1, 2048, b2, 1024, w[4], w[5], w[6]);
    stage_kernel<3, 16, 128, 8><<<dim3(32, 32), 128>>>(b2, 1024, outp, 512, w[7], w[8], w[9]);
}